// round 1
// baseline (speedup 1.0000x reference)
#include <cuda_runtime.h>

#define NJ 22
#define NF 8
#define SEQ 176
#define DM 256
#define HEADS 8
#define HD 32
#define BATCH 512
#define MROWS (BATCH*SEQ)   // 90112

typedef unsigned long long u64;

// PE table (22 joints x 256 dims) and QKV scratch (3 x 90112 x 256 fp32 = 277 MB)
__device__ float g_pe[NJ*DM];
__device__ float g_qkv[3ULL*(size_t)MROWS*(size_t)DM];

__device__ __forceinline__ u64 pack2(float x, float y){
    u64 r; asm("mov.b64 %0, {%1,%2};" : "=l"(r) : "f"(x), "f"(y)); return r;
}
__device__ __forceinline__ float2 unpack2(u64 v){
    float2 f; asm("mov.b64 {%0,%1}, %2;" : "=f"(f.x), "=f"(f.y) : "l"(v)); return f;
}
// Blackwell packed fp32x2 FMA (2x fp32 throughput)
__device__ __forceinline__ u64 ffma2(u64 a, u64 b, u64 c){
    u64 d; asm("fma.rn.f32x2 %0, %1, %2, %3;" : "=l"(d) : "l"(a), "l"(b), "l"(c)); return d;
}

// ---------------------------------------------------------------------------
// Positional-embedding table init (spatial: pos = joint id)
// ---------------------------------------------------------------------------
__global__ void pe_init_kernel() {
    int idx = blockIdx.x * blockDim.x + threadIdx.x;
    if (idx >= NJ*DM) return;
    int j = idx / DM;
    int d = idx - j*DM;
    // div = exp(-(ln 10000) * (d & ~1) / 256)
    float e = __expf(-9.210340371976184f * (float)(d & ~1) / (float)DM);
    float ang = (float)j * e;
    g_pe[idx] = (d & 1) ? cosf(ang) : sinf(ang);
}

// ---------------------------------------------------------------------------
// Fused (x + pe) @ [Wq | Wk | Wv]^T + b  ->  g_qkv
// M=90112, N=768, K=256. 64x64 tile, 256 threads, f32x2 packed FMA.
// Both X rows and W rows are K-contiguous -> load pairs along K directly.
// ---------------------------------------------------------------------------
__global__ __launch_bounds__(256) void qkv_gemm_kernel(
    const float* __restrict__ x,
    const float* __restrict__ wq, const float* __restrict__ bq,
    const float* __restrict__ wk, const float* __restrict__ bk,
    const float* __restrict__ wv, const float* __restrict__ bv)
{
    // As[kk][m]: packed (k_even,k_odd) pair for row m; stride 66 (even pad:
    // keeps 16B alignment for vector LDS, de-conflicts the transposing stores)
    __shared__ u64 As[8][66];
    __shared__ u64 Bs[8][66];

    const int m0 = blockIdx.x * 64;
    const int n0 = blockIdx.y * 64;          // 0..704
    const int which = n0 >> 8;               // 0=Q 1=K 2=V
    const float* wbase = (which == 0) ? wq : (which == 1) ? wk : wv;
    const float* bbase = (which == 0) ? bq : (which == 1) ? bk : bv;
    const int ncol0 = n0 & 255;

    const int t  = threadIdx.x;
    const int lr = t >> 2;            // 0..63 : row within tile (loader)
    const int lk = (t & 3) << 2;      // 0,4,8,12 : k offset (loader)
    const int tm = (t & 15) << 2;     // micro-tile rows
    const int tn = (t >> 4) << 2;     // micro-tile cols

    const int   rowm  = m0 + lr;
    const float* xrow  = x + (size_t)rowm * DM + lk;
    const float* perow = g_pe + (size_t)(rowm % NJ) * DM + lk;
    const float* wrow  = wbase + (size_t)(ncol0 + lr) * DM + lk;

    u64 acc[4][4];
#pragma unroll
    for (int i = 0; i < 4; i++)
#pragma unroll
        for (int j = 0; j < 4; j++) acc[i][j] = 0ULL;

    const int kk0 = lk >> 1;   // 0,2,4,6

    for (int kc = 0; kc < DM; kc += 16) {
        float4 xa = *(const float4*)(xrow + kc);
        float4 pa = *(const float4*)(perow + kc);
        float4 wb = *(const float4*)(wrow + kc);
        As[kk0    ][lr] = pack2(xa.x + pa.x, xa.y + pa.y);
        As[kk0 + 1][lr] = pack2(xa.z + pa.z, xa.w + pa.w);
        Bs[kk0    ][lr] = pack2(wb.x, wb.y);
        Bs[kk0 + 1][lr] = pack2(wb.z, wb.w);
        __syncthreads();
#pragma unroll
        for (int kk = 0; kk < 8; kk++) {
            ulonglong2 a01 = *(const ulonglong2*)&As[kk][tm];
            ulonglong2 a23 = *(const ulonglong2*)&As[kk][tm + 2];
            ulonglong2 b01 = *(const ulonglong2*)&Bs[kk][tn];
            ulonglong2 b23 = *(const ulonglong2*)&Bs[kk][tn + 2];
            u64 a[4] = {a01.x, a01.y, a23.x, a23.y};
            u64 b[4] = {b01.x, b01.y, b23.x, b23.y};
#pragma unroll
            for (int i = 0; i < 4; i++)
#pragma unroll
                for (int j = 0; j < 4; j++)
                    acc[i][j] = ffma2(a[i], b[j], acc[i][j]);
        }
        __syncthreads();
    }

    float* obase = g_qkv + (size_t)which * MROWS * DM;
#pragma unroll
    for (int i = 0; i < 4; i++) {
        int gm = m0 + tm + i;
        float4 o;
        float2 s;
        s = unpack2(acc[i][0]); o.x = s.x + s.y + bbase[ncol0 + tn + 0];
        s = unpack2(acc[i][1]); o.y = s.x + s.y + bbase[ncol0 + tn + 1];
        s = unpack2(acc[i][2]); o.z = s.x + s.y + bbase[ncol0 + tn + 2];
        s = unpack2(acc[i][3]); o.w = s.x + s.y + bbase[ncol0 + tn + 3];
        *(float4*)(obase + (size_t)gm * DM + (ncol0 + tn)) = o;
    }
}

// ---------------------------------------------------------------------------
// Frame-local attention. Block = (batch, frame), warp = head.
// The block-diagonal mask == softmax restricted to the 22 keys of the frame.
// Lane = query row; K/V head tiles staged in smem; all math f32x2 packed.
// ---------------------------------------------------------------------------
__global__ __launch_bounds__(256) void attention_kernel(float* __restrict__ out)
{
    __shared__ float ks[HEADS][NJ][HD];   // 22.5 KB
    __shared__ float vs[HEADS][NJ][HD];   // 22.5 KB

    const int bf   = blockIdx.x;
    const int b    = bf >> 3;
    const int f    = bf & 7;
    const int h    = threadIdx.x >> 5;
    const int lane = threadIdx.x & 31;

    const size_t row0 = (size_t)b * SEQ + (size_t)f * NJ;
    const float* Q = g_qkv;
    const float* K = g_qkv + (size_t)MROWS * DM;
    const float* V = g_qkv + 2ULL * (size_t)MROWS * DM;

    // Stage this head's K,V frame tile: lane = dim, loop over keys (coalesced 128B)
#pragma unroll
    for (int kj = 0; kj < NJ; kj++) {
        ks[h][kj][lane] = K[(row0 + kj) * DM + h * HD + lane];
        vs[h][kj][lane] = V[(row0 + kj) * DM + h * HD + lane];
    }
    __syncwarp();

    const int qi = (lane < NJ) ? lane : (NJ - 1);
    const u64* qp = (const u64*)(Q + (row0 + qi) * DM + h * HD);
    u64 q2[16];
#pragma unroll
    for (int i = 0; i < 16; i++) q2[i] = qp[i];

    // Scores: 22 dots of length 32 (16 FFMA2 each), K broadcast from smem
    const u64* ksp = (const u64*)&ks[h][0][0];
    float sc[NJ];
#pragma unroll
    for (int kj = 0; kj < NJ; kj++) {
        u64 acc = 0ULL;
#pragma unroll
        for (int d = 0; d < 16; d++) acc = ffma2(q2[d], ksp[kj * 16 + d], acc);
        float2 s = unpack2(acc);
        sc[kj] = (s.x + s.y) * 0.17677669529663687f;   // 1/sqrt(32)
    }

    // Per-lane softmax over the 22 frame keys
    float m = sc[0];
#pragma unroll
    for (int kj = 1; kj < NJ; kj++) m = fmaxf(m, sc[kj]);
    float sum = 0.f;
#pragma unroll
    for (int kj = 0; kj < NJ; kj++) { sc[kj] = __expf(sc[kj] - m); sum += sc[kj]; }
    const float inv = 1.0f / sum;

    // Output: out_row = sum_j p_j * v_j  (broadcast V from smem, packed FMA)
    const u64* vsp = (const u64*)&vs[h][0][0];
    u64 o2[16];
#pragma unroll
    for (int i = 0; i < 16; i++) o2[i] = 0ULL;
#pragma unroll
    for (int kj = 0; kj < NJ; kj++) {
        float p = sc[kj] * inv;
        u64 pp = pack2(p, p);
#pragma unroll
        for (int d = 0; d < 16; d++) o2[d] = ffma2(pp, vsp[kj * 16 + d], o2[d]);
    }

    if (lane < NJ) {
        u64* op = (u64*)(out + (row0 + qi) * DM + h * HD);
#pragma unroll
        for (int i = 0; i < 16; i++) op[i] = o2[i];
    }
}

// ---------------------------------------------------------------------------
extern "C" void kernel_launch(void* const* d_in, const int* in_sizes, int n_in,
                              void* d_out, int out_size)
{
    const float* x  = (const float*)d_in[0];
    const float* wq = (const float*)d_in[1];
    const float* bq = (const float*)d_in[2];
    const float* wk = (const float*)d_in[3];
    const float* bk = (const float*)d_in[4];
    const float* wv = (const float*)d_in[5];
    const float* bv = (const float*)d_in[6];
    float* out = (float*)d_out;

    pe_init_kernel<<<(NJ*DM + 255) / 256, 256>>>();

    dim3 ggrid(MROWS / 64, 768 / 64);   // 1408 x 12
    qkv_gemm_kernel<<<ggrid, 256>>>(x, wq, bq, wk, bk, wv, bv);

    attention_kernel<<<BATCH * NF, 256>>>(out);
}

// round 3
// speedup vs baseline: 2.5303x; 2.5303x over previous
#include <cuda_runtime.h>
#include <cuda_bf16.h>
#include <cstdint>

#define NJ 22
#define NF 8
#define SEQ 176
#define DM 256
#define HEADS 8
#define HD 32
#define BATCH 512
#define MROWS (BATCH*SEQ)   // 90112

typedef unsigned long long u64;

// PE table (22 x 256) and QKV scratch (3 x 90112 x 256 fp32 = 277 MB)
__device__ float g_pe[NJ*DM];
__device__ float g_qkv[3ULL*(size_t)MROWS*(size_t)DM];

// ---------------------------------------------------------------------------
// helpers
// ---------------------------------------------------------------------------
__device__ __forceinline__ uint32_t smem_u32(const void* p){
    uint32_t a;
    asm("{ .reg .u64 t; cvta.to.shared.u64 t, %1; cvt.u32.u64 %0, t; }" : "=r"(a) : "l"(p));
    return a;
}
__device__ __forceinline__ uint32_t sw128(uint32_t off){ return off ^ ((off >> 3) & 0x70); }

#define LDSM_X4(r0,r1,r2,r3,addr) \
    asm volatile("ldmatrix.sync.aligned.m8n8.x4.shared.b16 {%0,%1,%2,%3}, [%4];" \
        : "=r"(r0),"=r"(r1),"=r"(r2),"=r"(r3) : "r"(addr))
#define LDSM_X2(r0,r1,addr) \
    asm volatile("ldmatrix.sync.aligned.m8n8.x2.shared.b16 {%0,%1}, [%2];" \
        : "=r"(r0),"=r"(r1) : "r"(addr))
#define MMA16816(d,a0,a1,a2,a3,b0,b1) \
    asm volatile("mma.sync.aligned.m16n8k16.row.col.f32.bf16.bf16.f32 " \
        "{%0,%1,%2,%3},{%4,%5,%6,%7},{%8,%9},{%0,%1,%2,%3};" \
        : "+f"((d)[0]),"+f"((d)[1]),"+f"((d)[2]),"+f"((d)[3]) \
        : "r"(a0),"r"(a1),"r"(a2),"r"(a3),"r"(b0),"r"(b1))

// fp32x4 -> packed bf16 hi (4) and lo (4)
__device__ __forceinline__ void split4(float a, float b, float c, float d, u64& hi, u64& lo){
    __nv_bfloat16 ha = __float2bfloat16(a), hb = __float2bfloat16(b);
    __nv_bfloat16 hc = __float2bfloat16(c), hd = __float2bfloat16(d);
    __nv_bfloat16 la = __float2bfloat16(a - __bfloat162float(ha));
    __nv_bfloat16 lb = __float2bfloat16(b - __bfloat162float(hb));
    __nv_bfloat16 lc = __float2bfloat16(c - __bfloat162float(hc));
    __nv_bfloat16 ld = __float2bfloat16(d - __bfloat162float(hd));
    hi = (u64)__bfloat16_as_ushort(ha) | ((u64)__bfloat16_as_ushort(hb) << 16)
       | ((u64)__bfloat16_as_ushort(hc) << 32) | ((u64)__bfloat16_as_ushort(hd) << 48);
    lo = (u64)__bfloat16_as_ushort(la) | ((u64)__bfloat16_as_ushort(lb) << 16)
       | ((u64)__bfloat16_as_ushort(lc) << 32) | ((u64)__bfloat16_as_ushort(ld) << 48);
}

// fp32x2 packed FMA (attention kernel)
__device__ __forceinline__ u64 pack2(float x, float y){
    u64 r; asm("mov.b64 %0, {%1,%2};" : "=l"(r) : "f"(x), "f"(y)); return r;
}
__device__ __forceinline__ float2 unpack2(u64 v){
    float2 f; asm("mov.b64 {%0,%1}, %2;" : "=f"(f.x), "=f"(f.y) : "l"(v)); return f;
}
__device__ __forceinline__ u64 ffma2(u64 a, u64 b, u64 c){
    u64 d; asm("fma.rn.f32x2 %0, %1, %2, %3;" : "=l"(d) : "l"(a), "l"(b), "l"(c)); return d;
}

// ---------------------------------------------------------------------------
// PE table init
// ---------------------------------------------------------------------------
__global__ void pe_init_kernel() {
    int idx = blockIdx.x * blockDim.x + threadIdx.x;
    if (idx >= NJ*DM) return;
    int j = idx / DM;
    int d = idx - j*DM;
    float e = __expf(-9.210340371976184f * (float)(d & ~1) / (float)DM);
    float ang = (float)j * e;
    g_pe[idx] = (d & 1) ? cosf(ang) : sinf(ang);
}

// ---------------------------------------------------------------------------
// QKV GEMM via mma.sync bf16 3-term split:
// (x+pe)[90112,256] @ W^T[256,768] + b -> g_qkv (fp32)
// CTA tile 128x128, K chunks of 64, single smem stage (2 CTAs/SM overlap).
// ---------------------------------------------------------------------------
#define MT 128
#define NT 128
#define KC 64
#define TILE16K 16384                      // 128 x 64 bf16
#define GEMM_SMEM (4*TILE16K + 1024)       // Ah, Al, Bh, Bl + align pad

__global__ __launch_bounds__(256, 2) void qkv_mma_kernel(
    const float* __restrict__ x,
    const float* __restrict__ wq, const float* __restrict__ bq,
    const float* __restrict__ wk, const float* __restrict__ bk,
    const float* __restrict__ wv, const float* __restrict__ bv)
{
    extern __shared__ char dyn_raw[];
    char* dsm = (char*)(((uintptr_t)dyn_raw + 1023) & ~(uintptr_t)1023);
    char* Ah = dsm;
    char* Al = Ah + TILE16K;
    char* Bh = Al + TILE16K;
    char* Bl = Bh + TILE16K;
    const uint32_t uAh = smem_u32(Ah), uAl = smem_u32(Al);
    const uint32_t uBh = smem_u32(Bh), uBl = smem_u32(Bl);

    const int tid  = threadIdx.x;
    const int wid  = tid >> 5;
    const int lane = tid & 31;
    const int wm   = wid & 3;              // 4 m-warps x 32 rows
    const int wn   = wid >> 2;             // 2 n-warps x 64 cols

    const int n0    = blockIdx.x * NT;     // 0..640
    const int m0    = blockIdx.y * MT;
    const int which = n0 >> 8;             // 0=Q 1=K 2=V
    const int ncol0 = n0 & 255;
    const float* wbase = (which == 0) ? wq : (which == 1) ? wk : wv;
    const float* bbase = (which == 0) ? bq : (which == 1) ? bk : bv;

    // ldmatrix per-lane source coordinates
    const int a_row = wm*32 + (lane & 15);          // + mt*16
    const int a_kb  = (lane >> 4) * 16;             // byte offset within k16
    const int b_row = wn*64 + (lane & 7);           // + nt*8
    const int b_kb  = ((lane >> 3) & 1) * 16;

    float acc[2][8][4];
#pragma unroll
    for (int i = 0; i < 2; i++)
#pragma unroll
        for (int j = 0; j < 8; j++)
#pragma unroll
            for (int q = 0; q < 4; q++) acc[i][j][q] = 0.f;

    for (int c = 0; c < 4; c++) {
        __syncthreads();   // previous compute done before overwrite
        // ---- load A: 128 rows x 64 K of (x + pe), hi/lo split, swizzled ----
#pragma unroll
        for (int it = 0; it < 8; it++) {
            int idx = it*256 + tid;          // float4 slot
            int r   = idx >> 4;              // row 0..127
            int f4  = idx & 15;              // k = f4*4
            int gm  = m0 + r;
            const float4 xa = *(const float4*)(x + (size_t)gm*DM + c*KC + f4*4);
            const float4 pa = *(const float4*)(g_pe + (size_t)(gm % NJ)*DM + c*KC + f4*4);
            u64 hi, lo;
            split4(xa.x + pa.x, xa.y + pa.y, xa.z + pa.z, xa.w + pa.w, hi, lo);
            uint32_t off = sw128((uint32_t)(r*128 + f4*8));
            *(u64*)(Ah + off) = hi;
            *(u64*)(Al + off) = lo;
        }
        // ---- load B: 128 weight rows x 64 K ----
#pragma unroll
        for (int it = 0; it < 8; it++) {
            int idx = it*256 + tid;
            int r   = idx >> 4;
            int f4  = idx & 15;
            const float4 wb = *(const float4*)(wbase + (size_t)(ncol0 + r)*DM + c*KC + f4*4);
            u64 hi, lo;
            split4(wb.x, wb.y, wb.z, wb.w, hi, lo);
            uint32_t off = sw128((uint32_t)(r*128 + f4*8));
            *(u64*)(Bh + off) = hi;
            *(u64*)(Bl + off) = lo;
        }
        __syncthreads();

        // ---- compute: 4 k16 steps ----
#pragma unroll
        for (int k = 0; k < 4; k++) {
            const int kb = k*32;   // bytes
            uint32_t ao0 = sw128((uint32_t)( a_row      *128 + kb + a_kb));
            uint32_t ao1 = sw128((uint32_t)((a_row + 16)*128 + kb + a_kb));
            uint32_t ah0[4], ah1[4], al0[4], al1[4];
            LDSM_X4(ah0[0],ah0[1],ah0[2],ah0[3], uAh + ao0);
            LDSM_X4(ah1[0],ah1[1],ah1[2],ah1[3], uAh + ao1);
            LDSM_X4(al0[0],al0[1],al0[2],al0[3], uAl + ao0);
            LDSM_X4(al1[0],al1[1],al1[2],al1[3], uAl + ao1);
#pragma unroll
            for (int nt = 0; nt < 8; nt++) {
                uint32_t bo = sw128((uint32_t)((b_row + nt*8)*128 + kb + b_kb));
                uint32_t bh[2], bl[2];
                LDSM_X2(bh[0], bh[1], uBh + bo);
                LDSM_X2(bl[0], bl[1], uBl + bo);
                MMA16816(acc[0][nt], ah0[0],ah0[1],ah0[2],ah0[3], bh[0],bh[1]);
                MMA16816(acc[0][nt], ah0[0],ah0[1],ah0[2],ah0[3], bl[0],bl[1]);
                MMA16816(acc[0][nt], al0[0],al0[1],al0[2],al0[3], bh[0],bh[1]);
                MMA16816(acc[1][nt], ah1[0],ah1[1],ah1[2],ah1[3], bh[0],bh[1]);
                MMA16816(acc[1][nt], ah1[0],ah1[1],ah1[2],ah1[3], bl[0],bl[1]);
                MMA16816(acc[1][nt], al1[0],al1[1],al1[2],al1[3], bh[0],bh[1]);
            }
        }
    }

    // ---- epilogue: bias add + float2 stores ----
    float* obase = g_qkv + (size_t)which*MROWS*DM;
    const int mr = m0 + wm*32 + (lane >> 2);
    const int nc = ncol0 + wn*64 + (lane & 3)*2;
#pragma unroll
    for (int mt = 0; mt < 2; mt++) {
#pragma unroll
        for (int nt = 0; nt < 8; nt++) {
            const int col = nc + nt*8;
            const float b0 = bbase[col], b1 = bbase[col+1];
            float2 v0 = make_float2(acc[mt][nt][0] + b0, acc[mt][nt][1] + b1);
            float2 v1 = make_float2(acc[mt][nt][2] + b0, acc[mt][nt][3] + b1);
            *(float2*)(obase + (size_t)(mr + mt*16    )*DM + col) = v0;
            *(float2*)(obase + (size_t)(mr + mt*16 + 8)*DM + col) = v1;
        }
    }
}

// ---------------------------------------------------------------------------
// Frame-local attention: block = (batch, frame), warp = head.
// ---------------------------------------------------------------------------
__global__ __launch_bounds__(256) void attention_kernel(float* __restrict__ out)
{
    __shared__ float ks[HEADS][NJ][HD];
    __shared__ float vs[HEADS][NJ][HD];

    const int bf   = blockIdx.x;
    const int b    = bf >> 3;
    const int f    = bf & 7;
    const int h    = threadIdx.x >> 5;
    const int lane = threadIdx.x & 31;

    const size_t row0 = (size_t)b * SEQ + (size_t)f * NJ;
    const float* Q = g_qkv;
    const float* K = g_qkv + (size_t)MROWS * DM;
    const float* V = g_qkv + 2ULL * (size_t)MROWS * DM;

#pragma unroll
    for (int kj = 0; kj < NJ; kj++) {
        ks[h][kj][lane] = K[(row0 + kj) * DM + h * HD + lane];
        vs[h][kj][lane] = V[(row0 + kj) * DM + h * HD + lane];
    }
    __syncwarp();

    const int qi = (lane < NJ) ? lane : (NJ - 1);
    const u64* qp = (const u64*)(Q + (row0 + qi) * DM + h * HD);
    u64 q2[16];
#pragma unroll
    for (int i = 0; i < 16; i++) q2[i] = qp[i];

    const u64* ksp = (const u64*)&ks[h][0][0];
    float sc[NJ];
#pragma unroll
    for (int kj = 0; kj < NJ; kj++) {
        u64 acc = 0ULL;
#pragma unroll
        for (int d = 0; d < 16; d++) acc = ffma2(q2[d], ksp[kj * 16 + d], acc);
        float2 s = unpack2(acc);
        sc[kj] = (s.x + s.y) * 0.17677669529663687f;
    }

    float m = sc[0];
#pragma unroll
    for (int kj = 1; kj < NJ; kj++) m = fmaxf(m, sc[kj]);
    float sum = 0.f;
#pragma unroll
    for (int kj = 0; kj < NJ; kj++) { sc[kj] = __expf(sc[kj] - m); sum += sc[kj]; }
    const float inv = 1.0f / sum;

    const u64* vsp = (const u64*)&vs[h][0][0];
    u64 o2[16];
#pragma unroll
    for (int i = 0; i < 16; i++) o2[i] = 0ULL;
#pragma unroll
    for (int kj = 0; kj < NJ; kj++) {
        float p = sc[kj] * inv;
        u64 pp = pack2(p, p);
#pragma unroll
        for (int d = 0; d < 16; d++) o2[d] = ffma2(pp, vsp[kj * 16 + d], o2[d]);
    }

    if (lane < NJ) {
        u64* op = (u64*)(out + (row0 + qi) * DM + h * HD);
#pragma unroll
        for (int i = 0; i < 16; i++) op[i] = o2[i];
    }
}

// ---------------------------------------------------------------------------
extern "C" void kernel_launch(void* const* d_in, const int* in_sizes, int n_in,
                              void* d_out, int out_size)
{
    const float* x  = (const float*)d_in[0];
    const float* wq = (const float*)d_in[1];
    const float* bq = (const float*)d_in[2];
    const float* wk = (const float*)d_in[3];
    const float* bk = (const float*)d_in[4];
    const float* wv = (const float*)d_in[5];
    const float* bv = (const float*)d_in[6];
    float* out = (float*)d_out;

    cudaFuncSetAttribute(qkv_mma_kernel, cudaFuncAttributeMaxDynamicSharedMemorySize, GEMM_SMEM);

    pe_init_kernel<<<(NJ*DM + 255) / 256, 256>>>();

    dim3 ggrid(768 / NT, MROWS / MT);   // (6, 704); x-fastest shares A tile in L2
    qkv_mma_kernel<<<ggrid, 256, GEMM_SMEM>>>(x, wq, bq, wk, bk, wv, bv);

    attention_kernel<<<BATCH * NF, 256>>>(out);
}

// round 4
// speedup vs baseline: 2.9852x; 1.1798x over previous
#include <cuda_runtime.h>
#include <cuda_bf16.h>
#include <cstdint>

#define NJ 22
#define NF 8
#define SEQ 176
#define DM 256
#define HEADS 8
#define HD 32
#define BATCH 512
#define MROWS (BATCH*SEQ)   // 90112

typedef unsigned long long u64;

// Scratch: PE table, pre-split A (x+pe) hi/lo, pre-split W hi/lo, QKV fp32
__device__ float g_pe[NJ*DM];
__device__ __nv_bfloat16 g_Ah[(size_t)MROWS*DM];
__device__ __nv_bfloat16 g_Al[(size_t)MROWS*DM];
__device__ __nv_bfloat16 g_Wh[768*DM];
__device__ __nv_bfloat16 g_Wl[768*DM];
__device__ float g_qkv[3ULL*(size_t)MROWS*(size_t)DM];

// ---------------------------------------------------------------------------
// helpers
// ---------------------------------------------------------------------------
__device__ __forceinline__ uint32_t smem_u32(const void* p){
    uint32_t a;
    asm("{ .reg .u64 t; cvta.to.shared.u64 t, %1; cvt.u32.u64 %0, t; }" : "=r"(a) : "l"(p));
    return a;
}
__device__ __forceinline__ uint32_t sw128(uint32_t off){ return off ^ ((off >> 3) & 0x70); }

__device__ __forceinline__ void cpasync16(uint32_t dst, const void* src){
    asm volatile("cp.async.cg.shared.global [%0], [%1], 16;" :: "r"(dst), "l"(src) : "memory");
}
#define CPASYNC_COMMIT() asm volatile("cp.async.commit_group;" ::: "memory")
#define CPASYNC_WAIT0()  asm volatile("cp.async.wait_group 0;" ::: "memory")

#define LDSM_X4(r0,r1,r2,r3,addr) \
    asm volatile("ldmatrix.sync.aligned.m8n8.x4.shared.b16 {%0,%1,%2,%3}, [%4];" \
        : "=r"(r0),"=r"(r1),"=r"(r2),"=r"(r3) : "r"(addr))
#define LDSM_X2(r0,r1,addr) \
    asm volatile("ldmatrix.sync.aligned.m8n8.x2.shared.b16 {%0,%1}, [%2];" \
        : "=r"(r0),"=r"(r1) : "r"(addr))
#define MMA16816(d,a0,a1,a2,a3,b0,b1) \
    asm volatile("mma.sync.aligned.m16n8k16.row.col.f32.bf16.bf16.f32 " \
        "{%0,%1,%2,%3},{%4,%5,%6,%7},{%8,%9},{%0,%1,%2,%3};" \
        : "+f"((d)[0]),"+f"((d)[1]),"+f"((d)[2]),"+f"((d)[3]) \
        : "r"(a0),"r"(a1),"r"(a2),"r"(a3),"r"(b0),"r"(b1))

// fp32x4 -> packed bf16 hi (4) and lo (4)
__device__ __forceinline__ void split4(float a, float b, float c, float d, u64& hi, u64& lo){
    __nv_bfloat16 ha = __float2bfloat16(a), hb = __float2bfloat16(b);
    __nv_bfloat16 hc = __float2bfloat16(c), hd = __float2bfloat16(d);
    __nv_bfloat16 la = __float2bfloat16(a - __bfloat162float(ha));
    __nv_bfloat16 lb = __float2bfloat16(b - __bfloat162float(hb));
    __nv_bfloat16 lc = __float2bfloat16(c - __bfloat162float(hc));
    __nv_bfloat16 ld = __float2bfloat16(d - __bfloat162float(hd));
    hi = (u64)__bfloat16_as_ushort(ha) | ((u64)__bfloat16_as_ushort(hb) << 16)
       | ((u64)__bfloat16_as_ushort(hc) << 32) | ((u64)__bfloat16_as_ushort(hd) << 48);
    lo = (u64)__bfloat16_as_ushort(la) | ((u64)__bfloat16_as_ushort(lb) << 16)
       | ((u64)__bfloat16_as_ushort(lc) << 32) | ((u64)__bfloat16_as_ushort(ld) << 48);
}

// fp32x2 packed FMA (attention kernel)
__device__ __forceinline__ u64 pack2(float x, float y){
    u64 r; asm("mov.b64 %0, {%1,%2};" : "=l"(r) : "f"(x), "f"(y)); return r;
}
__device__ __forceinline__ float2 unpack2(u64 v){
    float2 f; asm("mov.b64 {%0,%1}, %2;" : "=f"(f.x), "=f"(f.y) : "l"(v)); return f;
}
__device__ __forceinline__ u64 ffma2(u64 a, u64 b, u64 c){
    u64 d; asm("fma.rn.f32x2 %0, %1, %2, %3;" : "=l"(d) : "l"(a), "l"(b), "l"(c)); return d;
}

// ---------------------------------------------------------------------------
// PE table init
// ---------------------------------------------------------------------------
__global__ void pe_init_kernel() {
    int idx = blockIdx.x * blockDim.x + threadIdx.x;
    if (idx >= NJ*DM) return;
    int j = idx / DM;
    int d = idx - j*DM;
    float e = __expf(-9.210340371976184f * (float)(d & ~1) / (float)DM);
    float ang = (float)j * e;
    g_pe[idx] = (d & 1) ? cosf(ang) : sinf(ang);
}

// ---------------------------------------------------------------------------
// W split: [wq|wk|wv] (768x256 fp32) -> g_Wh/g_Wl bf16
// ---------------------------------------------------------------------------
__global__ __launch_bounds__(256) void wsplit_kernel(
    const float* __restrict__ wq, const float* __restrict__ wk, const float* __restrict__ wv)
{
    int e4 = blockIdx.x * blockDim.x + threadIdx.x;    // float4 index, 49152 total
    if (e4 >= 768*DM/4) return;
    int row = e4 >> 6;                                 // 0..767
    const float* w = (row < 256) ? wq : (row < 512) ? wk : wv;
    int lrow = row & 255;
    int c4   = e4 & 63;
    float4 v = *(const float4*)(w + (size_t)lrow*DM + c4*4);
    u64 hi, lo;
    split4(v.x, v.y, v.z, v.w, hi, lo);
    *(u64*)(g_Wh + (size_t)e4*4) = hi;
    *(u64*)(g_Wl + (size_t)e4*4) = lo;
}

// ---------------------------------------------------------------------------
// A split: (x + pe) -> g_Ah/g_Al bf16   (90112x256)
// ---------------------------------------------------------------------------
__global__ __launch_bounds__(256) void xsplit_kernel(const float* __restrict__ x)
{
    int e4 = blockIdx.x * blockDim.x + threadIdx.x;    // float4 index, 5767168 total
    if (e4 >= MROWS*DM/4) return;
    int m  = e4 >> 6;
    int c4 = e4 & 63;
    float4 xa = *(const float4*)(x + (size_t)m*DM + c4*4);
    float4 pa = *(const float4*)(g_pe + (size_t)(m % NJ)*DM + c4*4);
    u64 hi, lo;
    split4(xa.x + pa.x, xa.y + pa.y, xa.z + pa.z, xa.w + pa.w, hi, lo);
    *(u64*)(g_Ah + (size_t)e4*4) = hi;
    *(u64*)(g_Al + (size_t)e4*4) = lo;
}

// ---------------------------------------------------------------------------
// QKV GEMM: pre-split bf16 3-term mma.sync. CTA tile 128x128, K chunks of 64.
// Loader = pure cp.async 16B copies into swizzled smem.
// ---------------------------------------------------------------------------
#define MT 128
#define NT 128
#define KC 64
#define TILE16K 16384                      // 128 x 64 bf16
#define GEMM_SMEM (4*TILE16K + 1024)       // Ah, Al, Bh, Bl + align pad

__global__ __launch_bounds__(256, 2) void qkv_mma_kernel(
    const float* __restrict__ bq, const float* __restrict__ bk, const float* __restrict__ bv)
{
    extern __shared__ char dyn_raw[];
    char* dsm = (char*)(((uintptr_t)dyn_raw + 1023) & ~(uintptr_t)1023);
    const uint32_t uAh = smem_u32(dsm);
    const uint32_t uAl = uAh + TILE16K;
    const uint32_t uBh = uAh + 2*TILE16K;
    const uint32_t uBl = uAh + 3*TILE16K;

    const int tid  = threadIdx.x;
    const int wid  = tid >> 5;
    const int lane = tid & 31;
    const int wm   = wid & 3;              // 4 m-warps x 32 rows
    const int wn   = wid >> 2;             // 2 n-warps x 64 cols

    const int n0    = blockIdx.x * NT;     // 0..640 (global weight-row base)
    const int m0    = blockIdx.y * MT;
    const int which = n0 >> 8;             // 0=Q 1=K 2=V
    const int ncol0 = n0 & 255;
    const float* bbase = (which == 0) ? bq : (which == 1) ? bk : bv;

    // loader coordinates: 2 threads per row, 4x16B segments each (64B half-row)
    const int lr = tid >> 1;               // row 0..127
    const int ls = (tid & 1) * 4;          // first segment (16B units)

    // ldmatrix per-lane source coordinates
    const int a_row = wm*32 + (lane & 15);
    const int a_kb  = (lane >> 4) * 16;
    const int b_row = wn*64 + (lane & 7);
    const int b_kb  = ((lane >> 3) & 1) * 16;

    float acc[2][8][4];
#pragma unroll
    for (int i = 0; i < 2; i++)
#pragma unroll
        for (int j = 0; j < 8; j++)
#pragma unroll
            for (int q = 0; q < 4; q++) acc[i][j][q] = 0.f;

    for (int c = 0; c < 4; c++) {
        __syncthreads();   // previous compute done before overwrite
        {
            const size_t a_src = ((size_t)(m0 + lr)*DM + c*KC);      // bf16 elements
            const size_t b_src = ((size_t)(n0 + lr)*DM + c*KC);
#pragma unroll
            for (int j = 0; j < 4; j++) {
                uint32_t off = sw128((uint32_t)(lr*128 + (ls + j)*16));
                const size_t sb = (size_t)(ls + j)*8;                // 8 bf16 per 16B
                cpasync16(uAh + off, g_Ah + a_src + sb);
                cpasync16(uAl + off, g_Al + a_src + sb);
                cpasync16(uBh + off, g_Wh + b_src + sb);
                cpasync16(uBl + off, g_Wl + b_src + sb);
            }
        }
        CPASYNC_COMMIT();
        CPASYNC_WAIT0();
        __syncthreads();

        // ---- compute: 4 k16 steps ----
#pragma unroll
        for (int k = 0; k < 4; k++) {
            const int kb = k*32;   // bytes
            uint32_t ao0 = sw128((uint32_t)( a_row      *128 + kb + a_kb));
            uint32_t ao1 = sw128((uint32_t)((a_row + 16)*128 + kb + a_kb));
            uint32_t ah0[4], ah1[4], al0[4], al1[4];
            LDSM_X4(ah0[0],ah0[1],ah0[2],ah0[3], uAh + ao0);
            LDSM_X4(ah1[0],ah1[1],ah1[2],ah1[3], uAh + ao1);
            LDSM_X4(al0[0],al0[1],al0[2],al0[3], uAl + ao0);
            LDSM_X4(al1[0],al1[1],al1[2],al1[3], uAl + ao1);
#pragma unroll
            for (int nt = 0; nt < 8; nt++) {
                uint32_t bo = sw128((uint32_t)((b_row + nt*8)*128 + kb + b_kb));
                uint32_t bh[2], bl[2];
                LDSM_X2(bh[0], bh[1], uBh + bo);
                LDSM_X2(bl[0], bl[1], uBl + bo);
                MMA16816(acc[0][nt], ah0[0],ah0[1],ah0[2],ah0[3], bh[0],bh[1]);
                MMA16816(acc[0][nt], ah0[0],ah0[1],ah0[2],ah0[3], bl[0],bl[1]);
                MMA16816(acc[0][nt], al0[0],al0[1],al0[2],al0[3], bh[0],bh[1]);
                MMA16816(acc[1][nt], ah1[0],ah1[1],ah1[2],ah1[3], bh[0],bh[1]);
                MMA16816(acc[1][nt], ah1[0],ah1[1],ah1[2],ah1[3], bl[0],bl[1]);
                MMA16816(acc[1][nt], al1[0],al1[1],al1[2],al1[3], bh[0],bh[1]);
            }
        }
    }

    // ---- epilogue: bias add + float2 stores ----
    float* obase = g_qkv + (size_t)which*MROWS*DM;
    const int mr = m0 + wm*32 + (lane >> 2);
    const int nc = ncol0 + wn*64 + (lane & 3)*2;
#pragma unroll
    for (int mt = 0; mt < 2; mt++) {
#pragma unroll
        for (int nt = 0; nt < 8; nt++) {
            const int col = nc + nt*8;
            const float b0 = bbase[col], b1 = bbase[col+1];
            float2 v0 = make_float2(acc[mt][nt][0] + b0, acc[mt][nt][1] + b1);
            float2 v1 = make_float2(acc[mt][nt][2] + b0, acc[mt][nt][3] + b1);
            *(float2*)(obase + (size_t)(mr + mt*16    )*DM + col) = v0;
            *(float2*)(obase + (size_t)(mr + mt*16 + 8)*DM + col) = v1;
        }
    }
}

// ---------------------------------------------------------------------------
// Frame-local attention: block = (batch, frame), warp = head.
// ---------------------------------------------------------------------------
__global__ __launch_bounds__(256) void attention_kernel(float* __restrict__ out)
{
    __shared__ float ks[HEADS][NJ][HD];
    __shared__ float vs[HEADS][NJ][HD];

    const int bf   = blockIdx.x;
    const int b    = bf >> 3;
    const int f    = bf & 7;
    const int h    = threadIdx.x >> 5;
    const int lane = threadIdx.x & 31;

    const size_t row0 = (size_t)b * SEQ + (size_t)f * NJ;
    const float* Q = g_qkv;
    const float* K = g_qkv + (size_t)MROWS * DM;
    const float* V = g_qkv + 2ULL * (size_t)MROWS * DM;

#pragma unroll
    for (int kj = 0; kj < NJ; kj++) {
        ks[h][kj][lane] = K[(row0 + kj) * DM + h * HD + lane];
        vs[h][kj][lane] = V[(row0 + kj) * DM + h * HD + lane];
    }
    __syncwarp();

    const int qi = (lane < NJ) ? lane : (NJ - 1);
    const u64* qp = (const u64*)(Q + (row0 + qi) * DM + h * HD);
    u64 q2[16];
#pragma unroll
    for (int i = 0; i < 16; i++) q2[i] = qp[i];

    const u64* ksp = (const u64*)&ks[h][0][0];
    float sc[NJ];
#pragma unroll
    for (int kj = 0; kj < NJ; kj++) {
        u64 acc = 0ULL;
#pragma unroll
        for (int d = 0; d < 16; d++) acc = ffma2(q2[d], ksp[kj * 16 + d], acc);
        float2 s = unpack2(acc);
        sc[kj] = (s.x + s.y) * 0.17677669529663687f;
    }

    float m = sc[0];
#pragma unroll
    for (int kj = 1; kj < NJ; kj++) m = fmaxf(m, sc[kj]);
    float sum = 0.f;
#pragma unroll
    for (int kj = 0; kj < NJ; kj++) { sc[kj] = __expf(sc[kj] - m); sum += sc[kj]; }
    const float inv = 1.0f / sum;

    const u64* vsp = (const u64*)&vs[h][0][0];
    u64 o2[16];
#pragma unroll
    for (int i = 0; i < 16; i++) o2[i] = 0ULL;
#pragma unroll
    for (int kj = 0; kj < NJ; kj++) {
        float p = sc[kj] * inv;
        u64 pp = pack2(p, p);
#pragma unroll
        for (int d = 0; d < 16; d++) o2[d] = ffma2(pp, vsp[kj * 16 + d], o2[d]);
    }

    if (lane < NJ) {
        u64* op = (u64*)(out + (row0 + qi) * DM + h * HD);
#pragma unroll
        for (int i = 0; i < 16; i++) op[i] = o2[i];
    }
}

// ---------------------------------------------------------------------------
extern "C" void kernel_launch(void* const* d_in, const int* in_sizes, int n_in,
                              void* d_out, int out_size)
{
    const float* x  = (const float*)d_in[0];
    const float* wq = (const float*)d_in[1];
    const float* bq = (const float*)d_in[2];
    const float* wk = (const float*)d_in[3];
    const float* bk = (const float*)d_in[4];
    const float* wv = (const float*)d_in[5];
    const float* bv = (const float*)d_in[6];
    float* out = (float*)d_out;

    cudaFuncSetAttribute(qkv_mma_kernel, cudaFuncAttributeMaxDynamicSharedMemorySize, GEMM_SMEM);

    pe_init_kernel<<<(NJ*DM + 255) / 256, 256>>>();
    wsplit_kernel<<<(768*DM/4 + 255) / 256, 256>>>(wq, wk, wv);
    xsplit_kernel<<<(MROWS*DM/4 + 255) / 256, 256>>>(x);

    dim3 ggrid(768 / NT, MROWS / MT);   // (6, 704); x-fastest shares A tile in L2
    qkv_mma_kernel<<<ggrid, 256, GEMM_SMEM>>>(bq, bk, bv);

    attention_kernel<<<BATCH * NF, 256>>>(out);
}

// round 5
// speedup vs baseline: 2.9926x; 1.0025x over previous
#include <cuda_runtime.h>
#include <cuda_bf16.h>
#include <cstdint>

#define NJ 22
#define NF 8
#define SEQ 176
#define DM 256
#define HEADS 8
#define HD 32
#define BATCH 512
#define MROWS (BATCH*SEQ)   // 90112

typedef unsigned long long u64;

// Scratch: PE table, pre-split A (x+pe) hi/lo, pre-split W hi/lo, QKV fp32
__device__ float g_pe[NJ*DM];
__device__ __nv_bfloat16 g_Ah[(size_t)MROWS*DM];
__device__ __nv_bfloat16 g_Al[(size_t)MROWS*DM];
__device__ __nv_bfloat16 g_Wh[768*DM];
__device__ __nv_bfloat16 g_Wl[768*DM];
__device__ float g_qkv[3ULL*(size_t)MROWS*(size_t)DM];

// ---------------------------------------------------------------------------
// helpers
// ---------------------------------------------------------------------------
__device__ __forceinline__ uint32_t smem_u32(const void* p){
    uint32_t a;
    asm("{ .reg .u64 t; cvta.to.shared.u64 t, %1; cvt.u32.u64 %0, t; }" : "=r"(a) : "l"(p));
    return a;
}
__device__ __forceinline__ uint32_t sw64(uint32_t off){ return off ^ ((off >> 3) & 0x30); }

__device__ __forceinline__ void cpasync16(uint32_t dst, const void* src){
    asm volatile("cp.async.cg.shared.global [%0], [%1], 16;" :: "r"(dst), "l"(src) : "memory");
}
#define CPASYNC_COMMIT() asm volatile("cp.async.commit_group;" ::: "memory")
#define CPASYNC_WAIT(n)  asm volatile("cp.async.wait_group %0;" :: "n"(n) : "memory")

#define LDSM_X4(r0,r1,r2,r3,addr) \
    asm volatile("ldmatrix.sync.aligned.m8n8.x4.shared.b16 {%0,%1,%2,%3}, [%4];" \
        : "=r"(r0),"=r"(r1),"=r"(r2),"=r"(r3) : "r"(addr))
#define LDSM_X2(r0,r1,addr) \
    asm volatile("ldmatrix.sync.aligned.m8n8.x2.shared.b16 {%0,%1}, [%2];" \
        : "=r"(r0),"=r"(r1) : "r"(addr))
#define MMA16816(d,a0,a1,a2,a3,b0,b1) \
    asm volatile("mma.sync.aligned.m16n8k16.row.col.f32.bf16.bf16.f32 " \
        "{%0,%1,%2,%3},{%4,%5,%6,%7},{%8,%9},{%0,%1,%2,%3};" \
        : "+f"((d)[0]),"+f"((d)[1]),"+f"((d)[2]),"+f"((d)[3]) \
        : "r"(a0),"r"(a1),"r"(a2),"r"(a3),"r"(b0),"r"(b1))

// fp32x4 -> packed bf16 hi (4) and lo (4)
__device__ __forceinline__ void split4(float a, float b, float c, float d, u64& hi, u64& lo){
    __nv_bfloat16 ha = __float2bfloat16(a), hb = __float2bfloat16(b);
    __nv_bfloat16 hc = __float2bfloat16(c), hd = __float2bfloat16(d);
    __nv_bfloat16 la = __float2bfloat16(a - __bfloat162float(ha));
    __nv_bfloat16 lb = __float2bfloat16(b - __bfloat162float(hb));
    __nv_bfloat16 lc = __float2bfloat16(c - __bfloat162float(hc));
    __nv_bfloat16 ld = __float2bfloat16(d - __bfloat162float(hd));
    hi = (u64)__bfloat16_as_ushort(ha) | ((u64)__bfloat16_as_ushort(hb) << 16)
       | ((u64)__bfloat16_as_ushort(hc) << 32) | ((u64)__bfloat16_as_ushort(hd) << 48);
    lo = (u64)__bfloat16_as_ushort(la) | ((u64)__bfloat16_as_ushort(lb) << 16)
       | ((u64)__bfloat16_as_ushort(lc) << 32) | ((u64)__bfloat16_as_ushort(ld) << 48);
}

// fp32x2 packed FMA (attention kernel)
__device__ __forceinline__ u64 pack2(float x, float y){
    u64 r; asm("mov.b64 %0, {%1,%2};" : "=l"(r) : "f"(x), "f"(y)); return r;
}
__device__ __forceinline__ float2 unpack2(u64 v){
    float2 f; asm("mov.b64 {%0,%1}, %2;" : "=f"(f.x), "=f"(f.y) : "l"(v)); return f;
}
__device__ __forceinline__ u64 ffma2(u64 a, u64 b, u64 c){
    u64 d; asm("fma.rn.f32x2 %0, %1, %2, %3;" : "=l"(d) : "l"(a), "l"(b), "l"(c)); return d;
}

// ---------------------------------------------------------------------------
// PE table init
// ---------------------------------------------------------------------------
__global__ void pe_init_kernel() {
    int idx = blockIdx.x * blockDim.x + threadIdx.x;
    if (idx >= NJ*DM) return;
    int j = idx / DM;
    int d = idx - j*DM;
    float e = __expf(-9.210340371976184f * (float)(d & ~1) / (float)DM);
    float ang = (float)j * e;
    g_pe[idx] = (d & 1) ? cosf(ang) : sinf(ang);
}

// ---------------------------------------------------------------------------
// W split: [wq|wk|wv] (768x256 fp32) -> g_Wh/g_Wl bf16
// ---------------------------------------------------------------------------
__global__ __launch_bounds__(256) void wsplit_kernel(
    const float* __restrict__ wq, const float* __restrict__ wk, const float* __restrict__ wv)
{
    int e4 = blockIdx.x * blockDim.x + threadIdx.x;
    if (e4 >= 768*DM/4) return;
    int row = e4 >> 6;
    const float* w = (row < 256) ? wq : (row < 512) ? wk : wv;
    int lrow = row & 255;
    int c4   = e4 & 63;
    float4 v = *(const float4*)(w + (size_t)lrow*DM + c4*4);
    u64 hi, lo;
    split4(v.x, v.y, v.z, v.w, hi, lo);
    *(u64*)(g_Wh + (size_t)e4*4) = hi;
    *(u64*)(g_Wl + (size_t)e4*4) = lo;
}

// ---------------------------------------------------------------------------
// A split: (x + pe) -> g_Ah/g_Al bf16   (90112x256)
// ---------------------------------------------------------------------------
__global__ __launch_bounds__(256) void xsplit_kernel(const float* __restrict__ x)
{
    int e4 = blockIdx.x * blockDim.x + threadIdx.x;
    if (e4 >= MROWS*DM/4) return;
    int m  = e4 >> 6;
    int c4 = e4 & 63;
    float4 xa = *(const float4*)(x + (size_t)m*DM + c4*4);
    float4 pa = *(const float4*)(g_pe + (size_t)(m % NJ)*DM + c4*4);
    u64 hi, lo;
    split4(xa.x + pa.x, xa.y + pa.y, xa.z + pa.z, xa.w + pa.w, hi, lo);
    *(u64*)(g_Ah + (size_t)e4*4) = hi;
    *(u64*)(g_Al + (size_t)e4*4) = lo;
}

// ---------------------------------------------------------------------------
// QKV GEMM: pre-split bf16 3-term mma.sync.
// CTA tile 128x128. KC=32, double-buffered cp.async pipeline (SW64 swizzle).
// ---------------------------------------------------------------------------
#define MT 128
#define NT 128
#define KC 32
#define NCHUNK (DM/KC)                 // 8
#define ARR8K 8192                     // 128 rows x 32 bf16
#define STAGE (4*ARR8K)                // Ah, Al, Bh, Bl = 32 KB
#define GEMM_SMEM (2*STAGE + 1024)

__global__ __launch_bounds__(256, 2) void qkv_mma_kernel(
    const float* __restrict__ bq, const float* __restrict__ bk, const float* __restrict__ bv)
{
    extern __shared__ char dyn_raw[];
    char* dsm = (char*)(((uintptr_t)dyn_raw + 1023) & ~(uintptr_t)1023);
    const uint32_t uS = smem_u32(dsm);

    const int tid  = threadIdx.x;
    const int wid  = tid >> 5;
    const int lane = tid & 31;
    const int wm   = wid & 3;              // 4 m-warps x 32 rows
    const int wn   = wid >> 2;             // 2 n-warps x 64 cols

    const int n0    = blockIdx.x * NT;     // 0..640 (global weight-row base)
    const int m0    = blockIdx.y * MT;
    const int which = n0 >> 8;             // 0=Q 1=K 2=V
    const int ncol0 = n0 & 255;
    const float* bbase = (which == 0) ? bq : (which == 1) ? bk : bv;

    // ldmatrix per-lane source coordinates (64B rows)
    const int a_row = wm*32 + (lane & 15);
    const int a_kb  = (lane >> 4) * 16;
    const int b_row = wn*64 + (lane & 7);
    const int b_kb  = ((lane >> 3) & 1) * 16;

    float acc[2][8][4];
#pragma unroll
    for (int i = 0; i < 2; i++)
#pragma unroll
        for (int j = 0; j < 8; j++)
#pragma unroll
            for (int q = 0; q < 4; q++) acc[i][j][q] = 0.f;

    // ---- loader lambda: chunk cc into stage ss ----
    auto load_chunk = [&](int cc, int ss){
        const uint32_t sb = uS + ss*STAGE;
#pragma unroll
        for (int j = 0; j < 2; j++) {
            int idx = tid*2 + j;           // 0..511
            int r   = idx >> 2;            // row 0..127
            int seg = idx & 3;             // 16B segment
            uint32_t off = sw64((uint32_t)(r*64 + seg*16));
            size_t a_src = (size_t)(m0 + r)*DM + cc*KC + seg*8;
            size_t b_src = (size_t)(n0 + r)*DM + cc*KC + seg*8;
            cpasync16(sb           + off, g_Ah + a_src);
            cpasync16(sb +   ARR8K + off, g_Al + a_src);
            cpasync16(sb + 2*ARR8K + off, g_Wh + b_src);
            cpasync16(sb + 3*ARR8K + off, g_Wl + b_src);
        }
    };

    // prologue: prefetch chunk 0
    load_chunk(0, 0);
    CPASYNC_COMMIT();

    for (int c = 0; c < NCHUNK; c++) {
        if (c + 1 < NCHUNK) {
            __syncthreads();               // all warps done with stage (c+1)&1
            load_chunk(c + 1, (c + 1) & 1);
            CPASYNC_COMMIT();
            CPASYNC_WAIT(1);               // chunk c landed
        } else {
            CPASYNC_WAIT(0);
        }
        __syncthreads();                   // publish stage c&1

        const uint32_t uAh = uS + (c & 1)*STAGE;
        const uint32_t uAl = uAh + ARR8K;
        const uint32_t uBh = uAh + 2*ARR8K;
        const uint32_t uBl = uAh + 3*ARR8K;

#pragma unroll
        for (int k = 0; k < 2; k++) {
            const int kb = k*32;   // bytes
            uint32_t ao0 = sw64((uint32_t)( a_row      *64 + kb + a_kb));
            uint32_t ao1 = sw64((uint32_t)((a_row + 16)*64 + kb + a_kb));
            uint32_t ah0[4], ah1[4], al0[4], al1[4];
            LDSM_X4(ah0[0],ah0[1],ah0[2],ah0[3], uAh + ao0);
            LDSM_X4(ah1[0],ah1[1],ah1[2],ah1[3], uAh + ao1);
            LDSM_X4(al0[0],al0[1],al0[2],al0[3], uAl + ao0);
            LDSM_X4(al1[0],al1[1],al1[2],al1[3], uAl + ao1);
#pragma unroll
            for (int nt = 0; nt < 8; nt++) {
                uint32_t bo = sw64((uint32_t)((b_row + nt*8)*64 + kb + b_kb));
                uint32_t bh[2], bl[2];
                LDSM_X2(bh[0], bh[1], uBh + bo);
                LDSM_X2(bl[0], bl[1], uBl + bo);
                MMA16816(acc[0][nt], ah0[0],ah0[1],ah0[2],ah0[3], bh[0],bh[1]);
                MMA16816(acc[0][nt], ah0[0],ah0[1],ah0[2],ah0[3], bl[0],bl[1]);
                MMA16816(acc[0][nt], al0[0],al0[1],al0[2],al0[3], bh[0],bh[1]);
                MMA16816(acc[1][nt], ah1[0],ah1[1],ah1[2],ah1[3], bh[0],bh[1]);
                MMA16816(acc[1][nt], ah1[0],ah1[1],ah1[2],ah1[3], bl[0],bl[1]);
                MMA16816(acc[1][nt], al1[0],al1[1],al1[2],al1[3], bh[0],bh[1]);
            }
        }
    }

    // ---- epilogue: bias add + float2 stores ----
    float* obase = g_qkv + (size_t)which*MROWS*DM;
    const int mr = m0 + wm*32 + (lane >> 2);
    const int nc = ncol0 + wn*64 + (lane & 3)*2;
#pragma unroll
    for (int mt = 0; mt < 2; mt++) {
#pragma unroll
        for (int nt = 0; nt < 8; nt++) {
            const int col = nc + nt*8;
            const float b0 = bbase[col], b1 = bbase[col+1];
            float2 v0 = make_float2(acc[mt][nt][0] + b0, acc[mt][nt][1] + b1);
            float2 v1 = make_float2(acc[mt][nt][2] + b0, acc[mt][nt][3] + b1);
            *(float2*)(obase + (size_t)(mr + mt*16    )*DM + col) = v0;
            *(float2*)(obase + (size_t)(mr + mt*16 + 8)*DM + col) = v1;
        }
    }
}

// ---------------------------------------------------------------------------
// Frame-local attention: block = (batch, frame), warp = head.
// ---------------------------------------------------------------------------
__global__ __launch_bounds__(256) void attention_kernel(float* __restrict__ out)
{
    __shared__ float ks[HEADS][NJ][HD];
    __shared__ float vs[HEADS][NJ][HD];

    const int bf   = blockIdx.x;
    const int b    = bf >> 3;
    const int f    = bf & 7;
    const int h    = threadIdx.x >> 5;
    const int lane = threadIdx.x & 31;

    const size_t row0 = (size_t)b * SEQ + (size_t)f * NJ;
    const float* Q = g_qkv;
    const float* K = g_qkv + (size_t)MROWS * DM;
    const float* V = g_qkv + 2ULL * (size_t)MROWS * DM;

#pragma unroll
    for (int kj = 0; kj < NJ; kj++) {
        ks[h][kj][lane] = K[(row0 + kj) * DM + h * HD + lane];
        vs[h][kj][lane] = V[(row0 + kj) * DM + h * HD + lane];
    }
    __syncwarp();

    const int qi = (lane < NJ) ? lane : (NJ - 1);
    const u64* qp = (const u64*)(Q + (row0 + qi) * DM + h * HD);
    u64 q2[16];
#pragma unroll
    for (int i = 0; i < 16; i++) q2[i] = qp[i];

    const u64* ksp = (const u64*)&ks[h][0][0];
    float sc[NJ];
#pragma unroll
    for (int kj = 0; kj < NJ; kj++) {
        u64 acc = 0ULL;
#pragma unroll
        for (int d = 0; d < 16; d++) acc = ffma2(q2[d], ksp[kj * 16 + d], acc);
        float2 s = unpack2(acc);
        sc[kj] = (s.x + s.y) * 0.17677669529663687f;
    }

    float m = sc[0];
#pragma unroll
    for (int kj = 1; kj < NJ; kj++) m = fmaxf(m, sc[kj]);
    float sum = 0.f;
#pragma unroll
    for (int kj = 0; kj < NJ; kj++) { sc[kj] = __expf(sc[kj] - m); sum += sc[kj]; }
    const float inv = 1.0f / sum;

    const u64* vsp = (const u64*)&vs[h][0][0];
    u64 o2[16];
#pragma unroll
    for (int i = 0; i < 16; i++) o2[i] = 0ULL;
#pragma unroll
    for (int kj = 0; kj < NJ; kj++) {
        float p = sc[kj] * inv;
        u64 pp = pack2(p, p);
#pragma unroll
        for (int d = 0; d < 16; d++) o2[d] = ffma2(pp, vsp[kj * 16 + d], o2[d]);
    }

    if (lane < NJ) {
        u64* op = (u64*)(out + (row0 + qi) * DM + h * HD);
#pragma unroll
        for (int i = 0; i < 16; i++) op[i] = o2[i];
    }
}

// ---------------------------------------------------------------------------
extern "C" void kernel_launch(void* const* d_in, const int* in_sizes, int n_in,
                              void* d_out, int out_size)
{
    const float* x  = (const float*)d_in[0];
    const float* wq = (const float*)d_in[1];
    const float* bq = (const float*)d_in[2];
    const float* wk = (const float*)d_in[3];
    const float* bk = (const float*)d_in[4];
    const float* wv = (const float*)d_in[5];
    const float* bv = (const float*)d_in[6];
    float* out = (float*)d_out;

    cudaFuncSetAttribute(qkv_mma_kernel, cudaFuncAttributeMaxDynamicSharedMemorySize, GEMM_SMEM);

    pe_init_kernel<<<(NJ*DM + 255) / 256, 256>>>();
    wsplit_kernel<<<(768*DM/4 + 255) / 256, 256>>>(wq, wk, wv);
    xsplit_kernel<<<(MROWS*DM/4 + 255) / 256, 256>>>(x);

    dim3 ggrid(768 / NT, MROWS / MT);   // (6, 704); x-fastest shares A tile in L2
    qkv_mma_kernel<<<ggrid, 256, GEMM_SMEM>>>(bq, bk, bv);

    attention_kernel<<<BATCH * NF, 256>>>(out);
}

// round 6
// speedup vs baseline: 3.6032x; 1.2041x over previous
#include <cuda_runtime.h>
#include <cuda_bf16.h>
#include <cstdint>

#define NJ 22
#define NF 8
#define SEQ 176
#define DM 256
#define HEADS 8
#define HD 32
#define BATCH 512
#define MROWS (BATCH*SEQ)   // 90112

typedef unsigned long long u64;

// Scratch: PE table, pre-split A (x+pe) hi/lo, pre-split W hi/lo, QKV fp32
__device__ float g_pe[NJ*DM];
__device__ __nv_bfloat16 g_Ah[(size_t)MROWS*DM];
__device__ __nv_bfloat16 g_Al[(size_t)MROWS*DM];
__device__ __nv_bfloat16 g_Wh[768*DM];
__device__ __nv_bfloat16 g_Wl[768*DM];
__device__ float g_qkv[3ULL*(size_t)MROWS*(size_t)DM];

// ---------------------------------------------------------------------------
// helpers
// ---------------------------------------------------------------------------
__device__ __forceinline__ uint32_t smem_u32(const void* p){
    uint32_t a;
    asm("{ .reg .u64 t; cvta.to.shared.u64 t, %1; cvt.u32.u64 %0, t; }" : "=r"(a) : "l"(p));
    return a;
}
__device__ __forceinline__ uint32_t sw64(uint32_t off){ return off ^ ((off >> 3) & 0x30); }

__device__ __forceinline__ void cpasync16(uint32_t dst, const void* src){
    asm volatile("cp.async.cg.shared.global [%0], [%1], 16;" :: "r"(dst), "l"(src) : "memory");
}
#define CPASYNC_COMMIT() asm volatile("cp.async.commit_group;" ::: "memory")
#define CPASYNC_WAIT(n)  asm volatile("cp.async.wait_group %0;" :: "n"(n) : "memory")

#define LDSM_X4(r0,r1,r2,r3,addr) \
    asm volatile("ldmatrix.sync.aligned.m8n8.x4.shared.b16 {%0,%1,%2,%3}, [%4];" \
        : "=r"(r0),"=r"(r1),"=r"(r2),"=r"(r3) : "r"(addr))
#define MMA16816(d,a0,a1,a2,a3,b0,b1) \
    asm volatile("mma.sync.aligned.m16n8k16.row.col.f32.bf16.bf16.f32 " \
        "{%0,%1,%2,%3},{%4,%5,%6,%7},{%8,%9},{%0,%1,%2,%3};" \
        : "+f"((d)[0]),"+f"((d)[1]),"+f"((d)[2]),"+f"((d)[3]) \
        : "r"(a0),"r"(a1),"r"(a2),"r"(a3),"r"(b0),"r"(b1))

// fp32x4 -> packed bf16 hi (4) and lo (4)
__device__ __forceinline__ void split4(float a, float b, float c, float d, u64& hi, u64& lo){
    __nv_bfloat16 ha = __float2bfloat16(a), hb = __float2bfloat16(b);
    __nv_bfloat16 hc = __float2bfloat16(c), hd = __float2bfloat16(d);
    __nv_bfloat16 la = __float2bfloat16(a - __bfloat162float(ha));
    __nv_bfloat16 lb = __float2bfloat16(b - __bfloat162float(hb));
    __nv_bfloat16 lc = __float2bfloat16(c - __bfloat162float(hc));
    __nv_bfloat16 ld = __float2bfloat16(d - __bfloat162float(hd));
    hi = (u64)__bfloat16_as_ushort(ha) | ((u64)__bfloat16_as_ushort(hb) << 16)
       | ((u64)__bfloat16_as_ushort(hc) << 32) | ((u64)__bfloat16_as_ushort(hd) << 48);
    lo = (u64)__bfloat16_as_ushort(la) | ((u64)__bfloat16_as_ushort(lb) << 16)
       | ((u64)__bfloat16_as_ushort(lc) << 32) | ((u64)__bfloat16_as_ushort(ld) << 48);
}

// fp32x2 packed FMA (attention kernel)
__device__ __forceinline__ u64 pack2(float x, float y){
    u64 r; asm("mov.b64 %0, {%1,%2};" : "=l"(r) : "f"(x), "f"(y)); return r;
}
__device__ __forceinline__ float2 unpack2(u64 v){
    float2 f; asm("mov.b64 {%0,%1}, %2;" : "=f"(f.x), "=f"(f.y) : "l"(v)); return f;
}
__device__ __forceinline__ u64 ffma2(u64 a, u64 b, u64 c){
    u64 d; asm("fma.rn.f32x2 %0, %1, %2, %3;" : "=l"(d) : "l"(a), "l"(b), "l"(c)); return d;
}

// ---------------------------------------------------------------------------
// PE table init
// ---------------------------------------------------------------------------
__global__ void pe_init_kernel() {
    int idx = blockIdx.x * blockDim.x + threadIdx.x;
    if (idx >= NJ*DM) return;
    int j = idx / DM;
    int d = idx - j*DM;
    float e = __expf(-9.210340371976184f * (float)(d & ~1) / (float)DM);
    float ang = (float)j * e;
    g_pe[idx] = (d & 1) ? cosf(ang) : sinf(ang);
}

// ---------------------------------------------------------------------------
// W split: [wq|wk|wv] (768x256 fp32) -> g_Wh/g_Wl bf16
// ---------------------------------------------------------------------------
__global__ __launch_bounds__(256) void wsplit_kernel(
    const float* __restrict__ wq, const float* __restrict__ wk, const float* __restrict__ wv)
{
    int e4 = blockIdx.x * blockDim.x + threadIdx.x;
    if (e4 >= 768*DM/4) return;
    int row = e4 >> 6;
    const float* w = (row < 256) ? wq : (row < 512) ? wk : wv;
    int lrow = row & 255;
    int c4   = e4 & 63;
    float4 v = *(const float4*)(w + (size_t)lrow*DM + c4*4);
    u64 hi, lo;
    split4(v.x, v.y, v.z, v.w, hi, lo);
    *(u64*)(g_Wh + (size_t)e4*4) = hi;
    *(u64*)(g_Wl + (size_t)e4*4) = lo;
}

// ---------------------------------------------------------------------------
// A split: (x + pe) -> g_Ah/g_Al bf16   (90112x256)
// ---------------------------------------------------------------------------
__global__ __launch_bounds__(256) void xsplit_kernel(const float* __restrict__ x)
{
    int e4 = blockIdx.x * blockDim.x + threadIdx.x;
    if (e4 >= MROWS*DM/4) return;
    int m  = e4 >> 6;
    int c4 = e4 & 63;
    float4 xa = *(const float4*)(x + (size_t)m*DM + c4*4);
    float4 pa = *(const float4*)(g_pe + (size_t)(m % NJ)*DM + c4*4);
    u64 hi, lo;
    split4(xa.x + pa.x, xa.y + pa.y, xa.z + pa.z, xa.w + pa.w, hi, lo);
    *(u64*)(g_Ah + (size_t)e4*4) = hi;
    *(u64*)(g_Al + (size_t)e4*4) = lo;
}

// ---------------------------------------------------------------------------
// QKV GEMM: pre-split bf16 3-term mma.sync.
// CTA tile 128x128. KC=32, double-buffered cp.async pipeline (SW64 swizzle).
// B fragments fetched two n-tiles at a time via ldmatrix.x4.
// ---------------------------------------------------------------------------
#define MT 128
#define NT 128
#define KC 32
#define NCHUNK (DM/KC)                 // 8
#define ARR8K 8192                     // 128 rows x 32 bf16
#define STAGE (4*ARR8K)                // Ah, Al, Bh, Bl = 32 KB
#define GEMM_SMEM (2*STAGE + 1024)

__global__ __launch_bounds__(256, 2) void qkv_mma_kernel(
    const float* __restrict__ bq, const float* __restrict__ bk, const float* __restrict__ bv)
{
    extern __shared__ char dyn_raw[];
    char* dsm = (char*)(((uintptr_t)dyn_raw + 1023) & ~(uintptr_t)1023);
    const uint32_t uS = smem_u32(dsm);

    const int tid  = threadIdx.x;
    const int wid  = tid >> 5;
    const int lane = tid & 31;
    const int wm   = wid & 3;              // 4 m-warps x 32 rows
    const int wn   = wid >> 2;             // 2 n-warps x 64 cols

    const int n0    = blockIdx.x * NT;     // 0..640 (global weight-row base)
    const int m0    = blockIdx.y * MT;
    const int which = n0 >> 8;             // 0=Q 1=K 2=V
    const int ncol0 = n0 & 255;
    const float* bbase = (which == 0) ? bq : (which == 1) ? bk : bv;

    // ldmatrix per-lane source coordinates (64B rows)
    const int a_row = wm*32 + (lane & 15);
    const int a_kb  = (lane >> 4) * 16;
    // B x4: lanes 0-15 -> n-tile nt2*2, lanes 16-31 -> nt2*2+1
    const int b_row = wn*64 + (lane & 7) + ((lane >> 4) & 1)*8;
    const int b_kb  = ((lane >> 3) & 1) * 16;

    float acc[2][8][4];
#pragma unroll
    for (int i = 0; i < 2; i++)
#pragma unroll
        for (int j = 0; j < 8; j++)
#pragma unroll
            for (int q = 0; q < 4; q++) acc[i][j][q] = 0.f;

    auto load_chunk = [&](int cc, int ss){
        const uint32_t sb = uS + ss*STAGE;
#pragma unroll
        for (int j = 0; j < 2; j++) {
            int idx = tid*2 + j;           // 0..511
            int r   = idx >> 2;            // row 0..127
            int seg = idx & 3;             // 16B segment
            uint32_t off = sw64((uint32_t)(r*64 + seg*16));
            size_t a_src = (size_t)(m0 + r)*DM + cc*KC + seg*8;
            size_t b_src = (size_t)(n0 + r)*DM + cc*KC + seg*8;
            cpasync16(sb           + off, g_Ah + a_src);
            cpasync16(sb +   ARR8K + off, g_Al + a_src);
            cpasync16(sb + 2*ARR8K + off, g_Wh + b_src);
            cpasync16(sb + 3*ARR8K + off, g_Wl + b_src);
        }
    };

    load_chunk(0, 0);
    CPASYNC_COMMIT();

    for (int c = 0; c < NCHUNK; c++) {
        if (c + 1 < NCHUNK) {
            __syncthreads();
            load_chunk(c + 1, (c + 1) & 1);
            CPASYNC_COMMIT();
            CPASYNC_WAIT(1);
        } else {
            CPASYNC_WAIT(0);
        }
        __syncthreads();

        const uint32_t uAh = uS + (c & 1)*STAGE;
        const uint32_t uAl = uAh + ARR8K;
        const uint32_t uBh = uAh + 2*ARR8K;
        const uint32_t uBl = uAh + 3*ARR8K;

#pragma unroll
        for (int k = 0; k < 2; k++) {
            const int kb = k*32;   // bytes
            uint32_t ao0 = sw64((uint32_t)( a_row      *64 + kb + a_kb));
            uint32_t ao1 = sw64((uint32_t)((a_row + 16)*64 + kb + a_kb));
            uint32_t ah0[4], ah1[4], al0[4], al1[4];
            LDSM_X4(ah0[0],ah0[1],ah0[2],ah0[3], uAh + ao0);
            LDSM_X4(ah1[0],ah1[1],ah1[2],ah1[3], uAh + ao1);
            LDSM_X4(al0[0],al0[1],al0[2],al0[3], uAl + ao0);
            LDSM_X4(al1[0],al1[1],al1[2],al1[3], uAl + ao1);
#pragma unroll
            for (int nt2 = 0; nt2 < 4; nt2++) {
                uint32_t bo = sw64((uint32_t)((b_row + nt2*16)*64 + kb + b_kb));
                uint32_t bh[4], bl[4];
                LDSM_X4(bh[0], bh[1], bh[2], bh[3], uBh + bo);
                LDSM_X4(bl[0], bl[1], bl[2], bl[3], uBl + bo);
                const int nt = nt2*2;
                MMA16816(acc[0][nt  ], ah0[0],ah0[1],ah0[2],ah0[3], bh[0],bh[1]);
                MMA16816(acc[0][nt  ], ah0[0],ah0[1],ah0[2],ah0[3], bl[0],bl[1]);
                MMA16816(acc[0][nt  ], al0[0],al0[1],al0[2],al0[3], bh[0],bh[1]);
                MMA16816(acc[1][nt  ], ah1[0],ah1[1],ah1[2],ah1[3], bh[0],bh[1]);
                MMA16816(acc[1][nt  ], ah1[0],ah1[1],ah1[2],ah1[3], bl[0],bl[1]);
                MMA16816(acc[1][nt  ], al1[0],al1[1],al1[2],al1[3], bh[0],bh[1]);
                MMA16816(acc[0][nt+1], ah0[0],ah0[1],ah0[2],ah0[3], bh[2],bh[3]);
                MMA16816(acc[0][nt+1], ah0[0],ah0[1],ah0[2],ah0[3], bl[2],bl[3]);
                MMA16816(acc[0][nt+1], al0[0],al0[1],al0[2],al0[3], bh[2],bh[3]);
                MMA16816(acc[1][nt+1], ah1[0],ah1[1],ah1[2],ah1[3], bh[2],bh[3]);
                MMA16816(acc[1][nt+1], ah1[0],ah1[1],ah1[2],ah1[3], bl[2],bl[3]);
                MMA16816(acc[1][nt+1], al1[0],al1[1],al1[2],al1[3], bh[2],bh[3]);
            }
        }
    }

    // ---- epilogue: bias add + float2 stores ----
    float* obase = g_qkv + (size_t)which*MROWS*DM;
    const int mr = m0 + wm*32 + (lane >> 2);
    const int nc = ncol0 + wn*64 + (lane & 3)*2;
#pragma unroll
    for (int mt = 0; mt < 2; mt++) {
#pragma unroll
        for (int nt = 0; nt < 8; nt++) {
            const int col = nc + nt*8;
            const float b0 = bbase[col], b1 = bbase[col+1];
            float2 v0 = make_float2(acc[mt][nt][0] + b0, acc[mt][nt][1] + b1);
            float2 v1 = make_float2(acc[mt][nt][2] + b0, acc[mt][nt][3] + b1);
            *(float2*)(obase + (size_t)(mr + mt*16    )*DM + col) = v0;
            *(float2*)(obase + (size_t)(mr + mt*16 + 8)*DM + col) = v1;
        }
    }
}

// ---------------------------------------------------------------------------
// Frame-local attention: block = (batch, frame), warp = head.
// Fully coalesced GMEM: Q/K/V staged lane=dim; O staged in smem then stored
// coalesced. Padded (33) Q/O tile makes per-lane row access conflict-free.
// ---------------------------------------------------------------------------
#define ATT_KV   (HEADS*NJ*HD)            // floats per K or V stage
#define ATT_QO   (HEADS*NJ*33)            // padded Q/O stage
#define ATT_SMEM ((2*ATT_KV + ATT_QO)*4)  // 68288 bytes

__global__ __launch_bounds__(256) void attention_kernel(float* __restrict__ out)
{
    extern __shared__ float sm[];
    float* ksb = sm;
    float* vsb = sm + ATT_KV;
    float* qsb = sm + 2*ATT_KV;

    const int bf   = blockIdx.x;
    const int b    = bf >> 3;
    const int f    = bf & 7;
    const int h    = threadIdx.x >> 5;
    const int lane = threadIdx.x & 31;

    float* ksh = ksb + h*NJ*HD;
    float* vsh = vsb + h*NJ*HD;
    float* qsh = qsb + h*NJ*33;

    const size_t row0 = (size_t)b * SEQ + (size_t)f * NJ;
    const float* Q = g_qkv;
    const float* K = g_qkv + (size_t)MROWS * DM;
    const float* V = g_qkv + 2ULL * (size_t)MROWS * DM;

    // Stage Q,K,V head tiles: lane = dim, loop joints (coalesced 128B lines)
#pragma unroll
    for (int kj = 0; kj < NJ; kj++) {
        const size_t src = (row0 + kj) * DM + h * HD + lane;
        ksh[kj*HD + lane] = K[src];
        vsh[kj*HD + lane] = V[src];
        qsh[kj*33 + lane] = Q[src];
    }
    __syncwarp();

    // Per-lane query row from padded smem (stride 33 -> conflict-free)
    const int qi = (lane < NJ) ? lane : (NJ - 1);
    u64 q2[16];
#pragma unroll
    for (int i = 0; i < 16; i++)
        q2[i] = pack2(qsh[qi*33 + 2*i], qsh[qi*33 + 2*i + 1]);
    __syncwarp();   // all lanes have consumed Q before O overwrites the tile

    // Scores: 22 dots of length 32 (broadcast K from smem)
    const u64* ksp = (const u64*)ksh;
    float sc[NJ];
#pragma unroll
    for (int kj = 0; kj < NJ; kj++) {
        u64 acc = 0ULL;
#pragma unroll
        for (int d = 0; d < 16; d++) acc = ffma2(q2[d], ksp[kj*16 + d], acc);
        float2 s = unpack2(acc);
        sc[kj] = (s.x + s.y) * 0.17677669529663687f;   // 1/sqrt(32)
    }

    float m = sc[0];
#pragma unroll
    for (int kj = 1; kj < NJ; kj++) m = fmaxf(m, sc[kj]);
    float sum = 0.f;
#pragma unroll
    for (int kj = 0; kj < NJ; kj++) { sc[kj] = __expf(sc[kj] - m); sum += sc[kj]; }
    const float inv = 1.0f / sum;

    const u64* vsp = (const u64*)vsh;
    u64 o2[16];
#pragma unroll
    for (int i = 0; i < 16; i++) o2[i] = 0ULL;
#pragma unroll
    for (int kj = 0; kj < NJ; kj++) {
        float p = sc[kj] * inv;
        u64 pp = pack2(p, p);
#pragma unroll
        for (int d = 0; d < 16; d++) o2[d] = ffma2(pp, vsp[kj*16 + d], o2[d]);
    }

    // Stage O into the (reused) padded tile, then store coalesced
    if (lane < NJ) {
#pragma unroll
        for (int i = 0; i < 16; i++) {
            float2 s = unpack2(o2[i]);
            qsh[qi*33 + 2*i    ] = s.x;
            qsh[qi*33 + 2*i + 1] = s.y;
        }
    }
    __syncwarp();
#pragma unroll
    for (int kj = 0; kj < NJ; kj++)
        out[(row0 + kj) * DM + h * HD + lane] = qsh[kj*33 + lane];
}

// ---------------------------------------------------------------------------
extern "C" void kernel_launch(void* const* d_in, const int* in_sizes, int n_in,
                              void* d_out, int out_size)
{
    const float* x  = (const float*)d_in[0];
    const float* wq = (const float*)d_in[1];
    const float* bq = (const float*)d_in[2];
    const float* wk = (const float*)d_in[3];
    const float* bk = (const float*)d_in[4];
    const float* wv = (const float*)d_in[5];
    const float* bv = (const float*)d_in[6];
    float* out = (float*)d_out;

    cudaFuncSetAttribute(qkv_mma_kernel, cudaFuncAttributeMaxDynamicSharedMemorySize, GEMM_SMEM);
    cudaFuncSetAttribute(attention_kernel, cudaFuncAttributeMaxDynamicSharedMemorySize, ATT_SMEM);

    pe_init_kernel<<<(NJ*DM + 255) / 256, 256>>>();
    wsplit_kernel<<<(768*DM/4 + 255) / 256, 256>>>(wq, wk, wv);
    xsplit_kernel<<<(MROWS*DM/4 + 255) / 256, 256>>>(x);

    dim3 ggrid(768 / NT, MROWS / MT);   // (6, 704); x-fastest shares A tile in L2
    qkv_mma_kernel<<<ggrid, 256, GEMM_SMEM>>>(bq, bk, bv);

    attention_kernel<<<BATCH * NF, 256, ATT_SMEM>>>(out);
}

// round 7
// speedup vs baseline: 4.7126x; 1.3079x over previous
#include <cuda_runtime.h>
#include <cuda_fp16.h>
#include <cstdint>

#define NJ 22
#define NF 8
#define SEQ 176
#define DM 256
#define HEADS 8
#define HD 32
#define BATCH 512
#define MROWS (BATCH*SEQ)   // 90112

typedef unsigned long long u64;

// Scratch: PE table, A=(x+pe) split fp16 hi/lo, W single fp16, QKV fp32
__device__ float g_pe[NJ*DM];
__device__ __half g_Ah[(size_t)MROWS*DM];
__device__ __half g_Al[(size_t)MROWS*DM];
__device__ __half g_Wf[768*DM];
__device__ float g_qkv[3ULL*(size_t)MROWS*(size_t)DM];

// ---------------------------------------------------------------------------
// helpers
// ---------------------------------------------------------------------------
__device__ __forceinline__ uint32_t smem_u32(const void* p){
    uint32_t a;
    asm("{ .reg .u64 t; cvta.to.shared.u64 t, %1; cvt.u32.u64 %0, t; }" : "=r"(a) : "l"(p));
    return a;
}
__device__ __forceinline__ uint32_t sw64(uint32_t off){ return off ^ ((off >> 3) & 0x30); }

__device__ __forceinline__ void cpasync16(uint32_t dst, const void* src){
    asm volatile("cp.async.cg.shared.global [%0], [%1], 16;" :: "r"(dst), "l"(src) : "memory");
}
#define CPASYNC_COMMIT() asm volatile("cp.async.commit_group;" ::: "memory")
#define CPASYNC_WAIT(n)  asm volatile("cp.async.wait_group %0;" :: "n"(n) : "memory")

#define LDSM_X4(r0,r1,r2,r3,addr) \
    asm volatile("ldmatrix.sync.aligned.m8n8.x4.shared.b16 {%0,%1,%2,%3}, [%4];" \
        : "=r"(r0),"=r"(r1),"=r"(r2),"=r"(r3) : "r"(addr))
#define MMAF16(d,a0,a1,a2,a3,b0,b1) \
    asm volatile("mma.sync.aligned.m16n8k16.row.col.f32.f16.f16.f32 " \
        "{%0,%1,%2,%3},{%4,%5,%6,%7},{%8,%9},{%0,%1,%2,%3};" \
        : "+f"((d)[0]),"+f"((d)[1]),"+f"((d)[2]),"+f"((d)[3]) \
        : "r"(a0),"r"(a1),"r"(a2),"r"(a3),"r"(b0),"r"(b1))

// fp32x4 -> packed fp16 hi (4) and lo (4)
__device__ __forceinline__ void split4h(float a, float b, float c, float d, u64& hi, u64& lo){
    __half ha = __float2half(a), hb = __float2half(b);
    __half hc = __float2half(c), hd = __float2half(d);
    __half la = __float2half(a - __half2float(ha));
    __half lb = __float2half(b - __half2float(hb));
    __half lc = __float2half(c - __half2float(hc));
    __half ld = __float2half(d - __half2float(hd));
    hi = (u64)__half_as_ushort(ha) | ((u64)__half_as_ushort(hb) << 16)
       | ((u64)__half_as_ushort(hc) << 32) | ((u64)__half_as_ushort(hd) << 48);
    lo = (u64)__half_as_ushort(la) | ((u64)__half_as_ushort(lb) << 16)
       | ((u64)__half_as_ushort(lc) << 32) | ((u64)__half_as_ushort(ld) << 48);
}

// fp32x2 packed FMA (attention kernel)
__device__ __forceinline__ u64 pack2(float x, float y){
    u64 r; asm("mov.b64 %0, {%1,%2};" : "=l"(r) : "f"(x), "f"(y)); return r;
}
__device__ __forceinline__ float2 unpack2(u64 v){
    float2 f; asm("mov.b64 {%0,%1}, %2;" : "=f"(f.x), "=f"(f.y) : "l"(v)); return f;
}
__device__ __forceinline__ u64 ffma2(u64 a, u64 b, u64 c){
    u64 d; asm("fma.rn.f32x2 %0, %1, %2, %3;" : "=l"(d) : "l"(a), "l"(b), "l"(c)); return d;
}

// ---------------------------------------------------------------------------
// PE table init
// ---------------------------------------------------------------------------
__global__ void pe_init_kernel() {
    int idx = blockIdx.x * blockDim.x + threadIdx.x;
    if (idx >= NJ*DM) return;
    int j = idx / DM;
    int d = idx - j*DM;
    float e = __expf(-9.210340371976184f * (float)(d & ~1) / (float)DM);
    float ang = (float)j * e;
    g_pe[idx] = (d & 1) ? cosf(ang) : sinf(ang);
}

// ---------------------------------------------------------------------------
// W convert: [wq|wk|wv] (768x256 fp32) -> g_Wf fp16
// ---------------------------------------------------------------------------
__global__ __launch_bounds__(256) void wsplit_kernel(
    const float* __restrict__ wq, const float* __restrict__ wk, const float* __restrict__ wv)
{
    int e4 = blockIdx.x * blockDim.x + threadIdx.x;
    if (e4 >= 768*DM/4) return;
    int row = e4 >> 6;
    const float* w = (row < 256) ? wq : (row < 512) ? wk : wv;
    int lrow = row & 255;
    int c4   = e4 & 63;
    float4 v = *(const float4*)(w + (size_t)lrow*DM + c4*4);
    u64 hv = (u64)__half_as_ushort(__float2half(v.x))
           | ((u64)__half_as_ushort(__float2half(v.y)) << 16)
           | ((u64)__half_as_ushort(__float2half(v.z)) << 32)
           | ((u64)__half_as_ushort(__float2half(v.w)) << 48);
    *(u64*)(g_Wf + (size_t)e4*4) = hv;
}

// ---------------------------------------------------------------------------
// A split: (x + pe) -> g_Ah/g_Al fp16   (90112x256)
// ---------------------------------------------------------------------------
__global__ __launch_bounds__(256) void xsplit_kernel(const float* __restrict__ x)
{
    int e4 = blockIdx.x * blockDim.x + threadIdx.x;
    if (e4 >= MROWS*DM/4) return;
    int m  = e4 >> 6;
    int c4 = e4 & 63;
    float4 xa = *(const float4*)(x + (size_t)m*DM + c4*4);
    float4 pa = *(const float4*)(g_pe + (size_t)(m % NJ)*DM + c4*4);
    u64 hi, lo;
    split4h(xa.x + pa.x, xa.y + pa.y, xa.z + pa.z, xa.w + pa.w, hi, lo);
    *(u64*)(g_Ah + (size_t)e4*4) = hi;
    *(u64*)(g_Al + (size_t)e4*4) = lo;
}

// ---------------------------------------------------------------------------
// QKV GEMM: fp16 2-term mma.sync (A split hi/lo, B single fp16).
// CTA tile 128x128. KC=32, double-buffered cp.async pipeline (SW64 swizzle).
// ---------------------------------------------------------------------------
#define MT 128
#define NT 128
#define KC 32
#define NCHUNK (DM/KC)                 // 8
#define ARR8K 8192                     // 128 rows x 32 fp16
#define STAGE (3*ARR8K)                // Ah, Al, Bf = 24 KB
#define GEMM_SMEM (2*STAGE + 1024)

__global__ __launch_bounds__(256, 2) void qkv_mma_kernel(
    const float* __restrict__ bq, const float* __restrict__ bk, const float* __restrict__ bv)
{
    extern __shared__ char dyn_raw[];
    char* dsm = (char*)(((uintptr_t)dyn_raw + 1023) & ~(uintptr_t)1023);
    const uint32_t uS = smem_u32(dsm);

    const int tid  = threadIdx.x;
    const int wid  = tid >> 5;
    const int lane = tid & 31;
    const int wm   = wid & 3;              // 4 m-warps x 32 rows
    const int wn   = wid >> 2;             // 2 n-warps x 64 cols

    const int n0    = blockIdx.x * NT;     // 0..640 (global weight-row base)
    const int m0    = blockIdx.y * MT;
    const int which = n0 >> 8;             // 0=Q 1=K 2=V
    const int ncol0 = n0 & 255;
    const float* bbase = (which == 0) ? bq : (which == 1) ? bk : bv;

    // ldmatrix per-lane source coordinates (64B rows)
    const int a_row = wm*32 + (lane & 15);
    const int a_kb  = (lane >> 4) * 16;
    // B x4: lanes 0-15 -> n-tile nt2*2, lanes 16-31 -> nt2*2+1
    const int b_row = wn*64 + (lane & 7) + ((lane >> 4) & 1)*8;
    const int b_kb  = ((lane >> 3) & 1) * 16;

    float acc[2][8][4];
#pragma unroll
    for (int i = 0; i < 2; i++)
#pragma unroll
        for (int j = 0; j < 8; j++)
#pragma unroll
            for (int q = 0; q < 4; q++) acc[i][j][q] = 0.f;

    auto load_chunk = [&](int cc, int ss){
        const uint32_t sb = uS + ss*STAGE;
#pragma unroll
        for (int j = 0; j < 6; j++) {
            int idx = j*256 + tid;         // 0..1535
            int arr = idx >> 9;            // 0=Ah 1=Al 2=Bf
            int w   = idx & 511;
            int r   = w >> 2;              // row 0..127
            int seg = w & 3;               // 16B segment
            uint32_t off = sw64((uint32_t)(r*64 + seg*16)) + arr*ARR8K;
            if (arr == 0) {
                cpasync16(sb + off, g_Ah + (size_t)(m0 + r)*DM + cc*KC + seg*8);
            } else if (arr == 1) {
                cpasync16(sb + off, g_Al + (size_t)(m0 + r)*DM + cc*KC + seg*8);
            } else {
                cpasync16(sb + off, g_Wf + (size_t)(n0 + r)*DM + cc*KC + seg*8);
            }
        }
    };

    load_chunk(0, 0);
    CPASYNC_COMMIT();

    for (int c = 0; c < NCHUNK; c++) {
        if (c + 1 < NCHUNK) {
            __syncthreads();
            load_chunk(c + 1, (c + 1) & 1);
            CPASYNC_COMMIT();
            CPASYNC_WAIT(1);
        } else {
            CPASYNC_WAIT(0);
        }
        __syncthreads();

        const uint32_t uAh = uS + (c & 1)*STAGE;
        const uint32_t uAl = uAh + ARR8K;
        const uint32_t uBf = uAh + 2*ARR8K;

#pragma unroll
        for (int k = 0; k < 2; k++) {
            const int kb = k*32;   // bytes
            uint32_t ao0 = sw64((uint32_t)( a_row      *64 + kb + a_kb));
            uint32_t ao1 = sw64((uint32_t)((a_row + 16)*64 + kb + a_kb));
            uint32_t ah0[4], ah1[4], al0[4], al1[4];
            LDSM_X4(ah0[0],ah0[1],ah0[2],ah0[3], uAh + ao0);
            LDSM_X4(ah1[0],ah1[1],ah1[2],ah1[3], uAh + ao1);
            LDSM_X4(al0[0],al0[1],al0[2],al0[3], uAl + ao0);
            LDSM_X4(al1[0],al1[1],al1[2],al1[3], uAl + ao1);
#pragma unroll
            for (int nt2 = 0; nt2 < 4; nt2++) {
                uint32_t bo = sw64((uint32_t)((b_row + nt2*16)*64 + kb + b_kb));
                uint32_t bf[4];
                LDSM_X4(bf[0], bf[1], bf[2], bf[3], uBf + bo);
                const int nt = nt2*2;
                // hi terms over 4 independent accumulators, then lo terms:
                // same-acc MMAs spaced by 4 -> no accumulator RAW stall
                MMAF16(acc[0][nt  ], ah0[0],ah0[1],ah0[2],ah0[3], bf[0],bf[1]);
                MMAF16(acc[1][nt  ], ah1[0],ah1[1],ah1[2],ah1[3], bf[0],bf[1]);
                MMAF16(acc[0][nt+1], ah0[0],ah0[1],ah0[2],ah0[3], bf[2],bf[3]);
                MMAF16(acc[1][nt+1], ah1[0],ah1[1],ah1[2],ah1[3], bf[2],bf[3]);
                MMAF16(acc[0][nt  ], al0[0],al0[1],al0[2],al0[3], bf[0],bf[1]);
                MMAF16(acc[1][nt  ], al1[0],al1[1],al1[2],al1[3], bf[0],bf[1]);
                MMAF16(acc[0][nt+1], al0[0],al0[1],al0[2],al0[3], bf[2],bf[3]);
                MMAF16(acc[1][nt+1], al1[0],al1[1],al1[2],al1[3], bf[2],bf[3]);
            }
        }
    }

    // ---- epilogue: bias add + float2 stores ----
    float* obase = g_qkv + (size_t)which*MROWS*DM;
    const int mr = m0 + wm*32 + (lane >> 2);
    const int nc = ncol0 + wn*64 + (lane & 3)*2;
#pragma unroll
    for (int mt = 0; mt < 2; mt++) {
#pragma unroll
        for (int nt = 0; nt < 8; nt++) {
            const int col = nc + nt*8;
            const float b0 = bbase[col], b1 = bbase[col+1];
            float2 v0 = make_float2(acc[mt][nt][0] + b0, acc[mt][nt][1] + b1);
            float2 v1 = make_float2(acc[mt][nt][2] + b0, acc[mt][nt][3] + b1);
            *(float2*)(obase + (size_t)(mr + mt*16    )*DM + col) = v0;
            *(float2*)(obase + (size_t)(mr + mt*16 + 8)*DM + col) = v1;
        }
    }
}

// ---------------------------------------------------------------------------
// Frame-local attention: block = (batch, frame), warp = head.
// Fully coalesced GMEM via smem staging; padded (33) Q/O tile.
// ---------------------------------------------------------------------------
#define ATT_KV   (HEADS*NJ*HD)            // floats per K or V stage
#define ATT_QO   (HEADS*NJ*33)            // padded Q/O stage
#define ATT_SMEM ((2*ATT_KV + ATT_QO)*4)  // 68288 bytes

__global__ __launch_bounds__(256) void attention_kernel(float* __restrict__ out)
{
    extern __shared__ float sm[];
    float* ksb = sm;
    float* vsb = sm + ATT_KV;
    float* qsb = sm + 2*ATT_KV;

    const int bf   = blockIdx.x;
    const int b    = bf >> 3;
    const int f    = bf & 7;
    const int h    = threadIdx.x >> 5;
    const int lane = threadIdx.x & 31;

    float* ksh = ksb + h*NJ*HD;
    float* vsh = vsb + h*NJ*HD;
    float* qsh = qsb + h*NJ*33;

    const size_t row0 = (size_t)b * SEQ + (size_t)f * NJ;
    const float* Q = g_qkv;
    const float* K = g_qkv + (size_t)MROWS * DM;
    const float* V = g_qkv + 2ULL * (size_t)MROWS * DM;

#pragma unroll
    for (int kj = 0; kj < NJ; kj++) {
        const size_t src = (row0 + kj) * DM + h * HD + lane;
        ksh[kj*HD + lane] = K[src];
        vsh[kj*HD + lane] = V[src];
        qsh[kj*33 + lane] = Q[src];
    }
    __syncwarp();

    const int qi = (lane < NJ) ? lane : (NJ - 1);
    u64 q2[16];
#pragma unroll
    for (int i = 0; i < 16; i++)
        q2[i] = pack2(qsh[qi*33 + 2*i], qsh[qi*33 + 2*i + 1]);
    __syncwarp();

    const u64* ksp = (const u64*)ksh;
    float sc[NJ];
#pragma unroll
    for (int kj = 0; kj < NJ; kj++) {
        u64 acc = 0ULL;
#pragma unroll
        for (int d = 0; d < 16; d++) acc = ffma2(q2[d], ksp[kj*16 + d], acc);
        float2 s = unpack2(acc);
        sc[kj] = (s.x + s.y) * 0.17677669529663687f;   // 1/sqrt(32)
    }

    float m = sc[0];
#pragma unroll
    for (int kj = 1; kj < NJ; kj++) m = fmaxf(m, sc[kj]);
    float sum = 0.f;
#pragma unroll
    for (int kj = 0; kj < NJ; kj++) { sc[kj] = __expf(sc[kj] - m); sum += sc[kj]; }
    const float inv = 1.0f / sum;

    const u64* vsp = (const u64*)vsh;
    u64 o2[16];
#pragma unroll
    for (int i = 0; i < 16; i++) o2[i] = 0ULL;
#pragma unroll
    for (int kj = 0; kj < NJ; kj++) {
        float p = sc[kj] * inv;
        u64 pp = pack2(p, p);
#pragma unroll
        for (int d = 0; d < 16; d++) o2[d] = ffma2(pp, vsp[kj*16 + d], o2[d]);
    }

    if (lane < NJ) {
#pragma unroll
        for (int i = 0; i < 16; i++) {
            float2 s = unpack2(o2[i]);
            qsh[qi*33 + 2*i    ] = s.x;
            qsh[qi*33 + 2*i + 1] = s.y;
        }
    }
    __syncwarp();
#pragma unroll
    for (int kj = 0; kj < NJ; kj++)
        out[(row0 + kj) * DM + h * HD + lane] = qsh[kj*33 + lane];
}

// ---------------------------------------------------------------------------
extern "C" void kernel_launch(void* const* d_in, const int* in_sizes, int n_in,
                              void* d_out, int out_size)
{
    const float* x  = (const float*)d_in[0];
    const float* wq = (const float*)d_in[1];
    const float* bq = (const float*)d_in[2];
    const float* wk = (const float*)d_in[3];
    const float* bk = (const float*)d_in[4];
    const float* wv = (const float*)d_in[5];
    const float* bv = (const float*)d_in[6];
    float* out = (float*)d_out;

    cudaFuncSetAttribute(qkv_mma_kernel, cudaFuncAttributeMaxDynamicSharedMemorySize, GEMM_SMEM);
    cudaFuncSetAttribute(attention_kernel, cudaFuncAttributeMaxDynamicSharedMemorySize, ATT_SMEM);

    pe_init_kernel<<<(NJ*DM + 255) / 256, 256>>>();
    wsplit_kernel<<<(768*DM/4 + 255) / 256, 256>>>(wq, wk, wv);
    xsplit_kernel<<<(MROWS*DM/4 + 255) / 256, 256>>>(x);

    dim3 ggrid(768 / NT, MROWS / MT);   // (6, 704); x-fastest shares A tile in L2
    qkv_mma_kernel<<<ggrid, 256, GEMM_SMEM>>>(bq, bk, bv);

    attention_kernel<<<BATCH * NF, 256, ATT_SMEM>>>(out);
}

// round 11
// speedup vs baseline: 4.7152x; 1.0006x over previous
#include <cuda_runtime.h>
#include <cuda_fp16.h>
#include <cstdint>

#define NJ 22
#define NF 8
#define SEQ 176
#define DM 256
#define HEADS 8
#define HD 32
#define BATCH 512
#define MROWS (BATCH*SEQ)   // 90112

typedef unsigned long long u64;

// Scratch: PE table, A=(x+pe) split fp16 hi/lo, W fp16, QKV fp16
__device__ float g_pe[NJ*DM];
__device__ __half g_Ah[(size_t)MROWS*DM];
__device__ __half g_Al[(size_t)MROWS*DM];
__device__ __half g_Wf[768*DM];
__device__ __half g_qkv[3ULL*(size_t)MROWS*(size_t)DM];

// ---------------------------------------------------------------------------
// helpers
// ---------------------------------------------------------------------------
__device__ __forceinline__ uint32_t smem_u32(const void* p){
    uint32_t a;
    asm("{ .reg .u64 t; cvta.to.shared.u64 t, %1; cvt.u32.u64 %0, t; }" : "=r"(a) : "l"(p));
    return a;
}
__device__ __forceinline__ uint32_t sw64(uint32_t off){ return off ^ ((off >> 3) & 0x30); }

__device__ __forceinline__ void cpasync16(uint32_t dst, const void* src){
    asm volatile("cp.async.cg.shared.global [%0], [%1], 16;" :: "r"(dst), "l"(src) : "memory");
}
#define CPASYNC_COMMIT() asm volatile("cp.async.commit_group;" ::: "memory")
#define CPASYNC_WAIT(n)  asm volatile("cp.async.wait_group %0;" :: "n"(n) : "memory")

#define LDSM_X4(r0,r1,r2,r3,addr) \
    asm volatile("ldmatrix.sync.aligned.m8n8.x4.shared.b16 {%0,%1,%2,%3}, [%4];" \
        : "=r"(r0),"=r"(r1),"=r"(r2),"=r"(r3) : "r"(addr))
#define MMAF16(d,a0,a1,a2,a3,b0,b1) \
    asm volatile("mma.sync.aligned.m16n8k16.row.col.f32.f16.f16.f32 " \
        "{%0,%1,%2,%3},{%4,%5,%6,%7},{%8,%9},{%0,%1,%2,%3};" \
        : "+f"((d)[0]),"+f"((d)[1]),"+f"((d)[2]),"+f"((d)[3]) \
        : "r"(a0),"r"(a1),"r"(a2),"r"(a3),"r"(b0),"r"(b1))

// fp32x4 -> packed fp16 hi (4) and lo (4)
__device__ __forceinline__ void split4h(float a, float b, float c, float d, u64& hi, u64& lo){
    __half ha = __float2half(a), hb = __float2half(b);
    __half hc = __float2half(c), hd = __float2half(d);
    __half la = __float2half(a - __half2float(ha));
    __half lb = __float2half(b - __half2float(hb));
    __half lc = __float2half(c - __half2float(hc));
    __half ld = __float2half(d - __half2float(hd));
    hi = (u64)__half_as_ushort(ha) | ((u64)__half_as_ushort(hb) << 16)
       | ((u64)__half_as_ushort(hc) << 32) | ((u64)__half_as_ushort(hd) << 48);
    lo = (u64)__half_as_ushort(la) | ((u64)__half_as_ushort(lb) << 16)
       | ((u64)__half_as_ushort(lc) << 32) | ((u64)__half_as_ushort(ld) << 48);
}

// fp32x2 packed FMA (attention kernel)
__device__ __forceinline__ u64 pack2(float x, float y){
    u64 r; asm("mov.b64 %0, {%1,%2};" : "=l"(r) : "f"(x), "f"(y)); return r;
}
__device__ __forceinline__ float2 unpack2(u64 v){
    float2 f; asm("mov.b64 {%0,%1}, %2;" : "=f"(f.x), "=f"(f.y) : "l"(v)); return f;
}
__device__ __forceinline__ u64 ffma2(u64 a, u64 b, u64 c){
    u64 d; asm("fma.rn.f32x2 %0, %1, %2, %3;" : "=l"(d) : "l"(a), "l"(b), "l"(c)); return d;
}

// ---------------------------------------------------------------------------
// PE table init
// ---------------------------------------------------------------------------
__global__ void pe_init_kernel() {
    int idx = blockIdx.x * blockDim.x + threadIdx.x;
    if (idx >= NJ*DM) return;
    int j = idx / DM;
    int d = idx - j*DM;
    float e = __expf(-9.210340371976184f * (float)(d & ~1) / (float)DM);
    float ang = (float)j * e;
    g_pe[idx] = (d & 1) ? cosf(ang) : sinf(ang);
}

// ---------------------------------------------------------------------------
// W convert: [wq|wk|wv] (768x256 fp32) -> g_Wf fp16
// ---------------------------------------------------------------------------
__global__ __launch_bounds__(256) void wsplit_kernel(
    const float* __restrict__ wq, const float* __restrict__ wk, const float* __restrict__ wv)
{
    int e4 = blockIdx.x * blockDim.x + threadIdx.x;
    if (e4 >= 768*DM/4) return;
    int row = e4 >> 6;
    const float* w = (row < 256) ? wq : (row < 512) ? wk : wv;
    int lrow = row & 255;
    int c4   = e4 & 63;
    float4 v = *(const float4*)(w + (size_t)lrow*DM + c4*4);
    u64 hv = (u64)__half_as_ushort(__float2half(v.x))
           | ((u64)__half_as_ushort(__float2half(v.y)) << 16)
           | ((u64)__half_as_ushort(__float2half(v.z)) << 32)
           | ((u64)__half_as_ushort(__float2half(v.w)) << 48);
    *(u64*)(g_Wf + (size_t)e4*4) = hv;
}

// ---------------------------------------------------------------------------
// A split: (x + pe) -> g_Ah/g_Al fp16   (90112x256)
// ---------------------------------------------------------------------------
__global__ __launch_bounds__(256) void xsplit_kernel(const float* __restrict__ x)
{
    int e4 = blockIdx.x * blockDim.x + threadIdx.x;
    if (e4 >= MROWS*DM/4) return;
    int m  = e4 >> 6;
    int c4 = e4 & 63;
    float4 xa = *(const float4*)(x + (size_t)m*DM + c4*4);
    float4 pa = *(const float4*)(g_pe + (size_t)(m % NJ)*DM + c4*4);
    u64 hi, lo;
    split4h(xa.x + pa.x, xa.y + pa.y, xa.z + pa.z, xa.w + pa.w, hi, lo);
    *(u64*)(g_Ah + (size_t)e4*4) = hi;
    *(u64*)(g_Al + (size_t)e4*4) = lo;
}

// ---------------------------------------------------------------------------
// QKV GEMM: fp16 2-term mma.sync (A split hi/lo, B single fp16).
// CTA tile 128x128. KC=32, 3-stage cp.async pipeline, 1 syncthreads/chunk.
// Output stored as fp16.
// ---------------------------------------------------------------------------
#define MT 128
#define NT 128
#define KC 32
#define NCHUNK (DM/KC)                 // 8
#define ARR8K 8192                     // 128 rows x 32 fp16
#define STAGE (3*ARR8K)                // Ah, Al, Bf = 24 KB
#define NSTAGE 3
#define GEMM_SMEM (NSTAGE*STAGE + 1024)

__device__ __forceinline__ void gemm_load_chunk(uint32_t uS, int m0, int n0,
                                                int cc, int ss, int tid)
{
    const uint32_t sb = uS + ss*STAGE;
#pragma unroll
    for (int j = 0; j < 6; j++) {
        int idx = j*256 + tid;         // 0..1535
        int arr = idx >> 9;            // 0=Ah 1=Al 2=Bf
        int w   = idx & 511;
        int r   = w >> 2;              // row 0..127
        int seg = w & 3;               // 16B segment
        uint32_t off = sw64((uint32_t)(r*64 + seg*16)) + arr*ARR8K;
        if (arr == 0) {
            cpasync16(sb + off, g_Ah + (size_t)(m0 + r)*DM + cc*KC + seg*8);
        } else if (arr == 1) {
            cpasync16(sb + off, g_Al + (size_t)(m0 + r)*DM + cc*KC + seg*8);
        } else {
            cpasync16(sb + off, g_Wf + (size_t)(n0 + r)*DM + cc*KC + seg*8);
        }
    }
}

__global__ __launch_bounds__(256, 2) void qkv_mma_kernel(
    const float* __restrict__ bq, const float* __restrict__ bk, const float* __restrict__ bv)
{
    extern __shared__ char dyn_raw[];
    char* dsm = (char*)(((uintptr_t)dyn_raw + 1023) & ~(uintptr_t)1023);
    const uint32_t uS = smem_u32(dsm);

    const int tid  = threadIdx.x;
    const int wid  = tid >> 5;
    const int lane = tid & 31;
    const int wm   = wid & 3;              // 4 m-warps x 32 rows
    const int wn   = wid >> 2;             // 2 n-warps x 64 cols

    const int n0    = blockIdx.x * NT;     // 0..640 (global weight-row base)
    const int m0    = blockIdx.y * MT;
    const int which = n0 >> 8;             // 0=Q 1=K 2=V
    const int ncol0 = n0 & 255;
    const float* bbase = (which == 0) ? bq : (which == 1) ? bk : bv;

    // ldmatrix per-lane source coordinates (64B rows)
    const int a_row = wm*32 + (lane & 15);
    const int a_kb  = (lane >> 4) * 16;
    const int b_row = wn*64 + (lane & 7) + ((lane >> 4) & 1)*8;
    const int b_kb  = ((lane >> 3) & 1) * 16;

    float acc[2][8][4];
#pragma unroll
    for (int i = 0; i < 2; i++)
#pragma unroll
        for (int j = 0; j < 8; j++)
#pragma unroll
            for (int q = 0; q < 4; q++) acc[i][j][q] = 0.f;

    // prologue: 2 chunks in flight
    gemm_load_chunk(uS, m0, n0, 0, 0, tid);
    CPASYNC_COMMIT();
    gemm_load_chunk(uS, m0, n0, 1, 1, tid);
    CPASYNC_COMMIT();

    for (int c = 0; c < NCHUNK; c++) {
        if (c + 2 < NCHUNK) {
            CPASYNC_WAIT(1);               // chunk c landed
            __syncthreads();               // publish c; stage (c+2)%3 free
            gemm_load_chunk(uS, m0, n0, c + 2, (c + 2) % NSTAGE, tid);
            CPASYNC_COMMIT();
        } else if (c + 1 < NCHUNK) {
            CPASYNC_WAIT(1);
            __syncthreads();
        } else {
            CPASYNC_WAIT(0);
            __syncthreads();
        }

        const uint32_t uAh = uS + (c % NSTAGE)*STAGE;
        const uint32_t uAl = uAh + ARR8K;
        const uint32_t uBf = uAh + 2*ARR8K;

#pragma unroll
        for (int k = 0; k < 2; k++) {
            const int kb = k*32;   // bytes
            uint32_t ao0 = sw64((uint32_t)( a_row      *64 + kb + a_kb));
            uint32_t ao1 = sw64((uint32_t)((a_row + 16)*64 + kb + a_kb));
            uint32_t ah0[4], ah1[4], al0[4], al1[4];
            LDSM_X4(ah0[0],ah0[1],ah0[2],ah0[3], uAh + ao0);
            LDSM_X4(ah1[0],ah1[1],ah1[2],ah1[3], uAh + ao1);
            LDSM_X4(al0[0],al0[1],al0[2],al0[3], uAl + ao0);
            LDSM_X4(al1[0],al1[1],al1[2],al1[3], uAl + ao1);
#pragma unroll
            for (int nt2 = 0; nt2 < 4; nt2++) {
                uint32_t bo = sw64((uint32_t)((b_row + nt2*16)*64 + kb + b_kb));
                uint32_t bf[4];
                LDSM_X4(bf[0], bf[1], bf[2], bf[3], uBf + bo);
                const int nt = nt2*2;
                // same-acc MMAs spaced by 4 independent ones
                MMAF16(acc[0][nt  ], ah0[0],ah0[1],ah0[2],ah0[3], bf[0],bf[1]);
                MMAF16(acc[1][nt  ], ah1[0],ah1[1],ah1[2],ah1[3], bf[0],bf[1]);
                MMAF16(acc[0][nt+1], ah0[0],ah0[1],ah0[2],ah0[3], bf[2],bf[3]);
                MMAF16(acc[1][nt+1], ah1[0],ah1[1],ah1[2],ah1[3], bf[2],bf[3]);
                MMAF16(acc[0][nt  ], al0[0],al0[1],al0[2],al0[3], bf[0],bf[1]);
                MMAF16(acc[1][nt  ], al1[0],al1[1],al1[2],al1[3], bf[0],bf[1]);
                MMAF16(acc[0][nt+1], al0[0],al0[1],al0[2],al0[3], bf[2],bf[3]);
                MMAF16(acc[1][nt+1], al1[0],al1[1],al1[2],al1[3], bf[2],bf[3]);
            }
        }
    }

    // ---- epilogue: bias add + fp16 stores ----
    __half* obase = g_qkv + (size_t)which*MROWS*DM;
    const int mr = m0 + wm*32 + (lane >> 2);
    const int nc = ncol0 + wn*64 + (lane & 3)*2;
#pragma unroll
    for (int mt = 0; mt < 2; mt++) {
#pragma unroll
        for (int nt = 0; nt < 8; nt++) {
            const int col = nc + nt*8;
            const float b0 = bbase[col], b1 = bbase[col+1];
            __half2 h0 = __floats2half2_rn(acc[mt][nt][0] + b0, acc[mt][nt][1] + b1);
            __half2 h1 = __floats2half2_rn(acc[mt][nt][2] + b0, acc[mt][nt][3] + b1);
            *(__half2*)(obase + (size_t)(mr + mt*16    )*DM + col) = h0;
            *(__half2*)(obase + (size_t)(mr + mt*16 + 8)*DM + col) = h1;
        }
    }
}

// ---------------------------------------------------------------------------
// Frame-local attention: block = (batch, frame), warp = head.
// fp16 QKV in, fp32 out. Coalesced GMEM via smem staging; padded (33) Q/O tile.
// ---------------------------------------------------------------------------
#define ATT_KV   (HEADS*NJ*HD)            // floats per K or V stage
#define ATT_QO   (HEADS*NJ*33)            // padded Q/O stage
#define ATT_SMEM ((2*ATT_KV + ATT_QO)*4)  // 68288 bytes

__global__ __launch_bounds__(256) void attention_kernel(float* __restrict__ out)
{
    extern __shared__ float sm[];
    float* ksb = sm;
    float* vsb = sm + ATT_KV;
    float* qsb = sm + 2*ATT_KV;

    const int bf   = blockIdx.x;
    const int b    = bf >> 3;
    const int f    = bf & 7;
    const int h    = threadIdx.x >> 5;
    const int lane = threadIdx.x & 31;

    float* ksh = ksb + h*NJ*HD;
    float* vsh = vsb + h*NJ*HD;
    float* qsh = qsb + h*NJ*33;

    const size_t row0 = (size_t)b * SEQ + (size_t)f * NJ;
    const __half* Q = g_qkv;
    const __half* K = g_qkv + (size_t)MROWS * DM;
    const __half* V = g_qkv + 2ULL * (size_t)MROWS * DM;

#pragma unroll
    for (int kj = 0; kj < NJ; kj++) {
        const size_t src = (row0 + kj) * DM + h * HD + lane;
        ksh[kj*HD + lane] = __half2float(K[src]);
        vsh[kj*HD + lane] = __half2float(V[src]);
        qsh[kj*33 + lane] = __half2float(Q[src]);
    }
    __syncwarp();

    const int qi = (lane < NJ) ? lane : (NJ - 1);
    u64 q2[16];
#pragma unroll
    for (int i = 0; i < 16; i++)
        q2[i] = pack2(qsh[qi*33 + 2*i], qsh[qi*33 + 2*i + 1]);
    __syncwarp();

    const u64* ksp = (const u64*)ksh;
    float sc[NJ];
#pragma unroll
    for (int kj = 0; kj < NJ; kj++) {
        u64 acc = 0ULL;
#pragma unroll
        for (int d = 0; d < 16; d++) acc = ffma2(q2[d], ksp[kj*16 + d], acc);
        float2 s = unpack2(acc);
        sc[kj] = (s.x + s.y) * 0.17677669529663687f;   // 1/sqrt(32)
    }

    float m = sc[0];
#pragma unroll
    for (int kj = 1; kj < NJ; kj++) m = fmaxf(m, sc[kj]);
    float sum = 0.f;
#pragma unroll
    for (int kj = 0; kj < NJ; kj++) { sc[kj] = __expf(sc[kj] - m); sum += sc[kj]; }
    const float inv = 1.0f / sum;

    const u64* vsp = (const u64*)vsh;
    u64 o2[16];
#pragma unroll
    for (int i = 0; i < 16; i++) o2[i] = 0ULL;
#pragma unroll
    for (int kj = 0; kj < NJ; kj++) {
        float p = sc[kj] * inv;
        u64 pp = pack2(p, p);
#pragma unroll
        for (int d = 0; d < 16; d++) o2[d] = ffma2(pp, vsp[kj*16 + d], o2[d]);
    }

    if (lane < NJ) {
#pragma unroll
        for (int i = 0; i < 16; i++) {
            float2 s = unpack2(o2[i]);
            qsh[qi*33 + 2*i    ] = s.x;
            qsh[qi*33 + 2*i + 1] = s.y;
        }
    }
    __syncwarp();
#pragma unroll
    for (int kj = 0; kj < NJ; kj++)
        out[(row0 + kj) * DM + h * HD + lane] = qsh[kj*33 + lane];
}

// ---------------------------------------------------------------------------
extern "C" void kernel_launch(void* const* d_in, const int* in_sizes, int n_in,
                              void* d_out, int out_size)
{
    const float* x  = (const float*)d_in[0];
    const float* wq = (const float*)d_in[1];
    const float* bq = (const float*)d_in[2];
    const float* wk = (const float*)d_in[3];
    const float* bk = (const float*)d_in[4];
    const float* wv = (const float*)d_in[5];
    const float* bv = (const float*)d_in[6];
    float* out = (float*)d_out;

    cudaFuncSetAttribute(qkv_mma_kernel, cudaFuncAttributeMaxDynamicSharedMemorySize, GEMM_SMEM);
    cudaFuncSetAttribute(attention_kernel, cudaFuncAttributeMaxDynamicSharedMemorySize, ATT_SMEM);

    pe_init_kernel<<<(NJ*DM + 255) / 256, 256>>>();
    wsplit_kernel<<<(768*DM/4 + 255) / 256, 256>>>(wq, wk, wv);
    xsplit_kernel<<<(MROWS*DM/4 + 255) / 256, 256>>>(x);

    dim3 ggrid(768 / NT, MROWS / MT);   // (6, 704); x-fastest shares A tile in L2
    qkv_mma_kernel<<<ggrid, 256, GEMM_SMEM>>>(bq, bk, bv);

    attention_kernel<<<BATCH * NF, 256, ATT_SMEM>>>(out);
}

// round 12
// speedup vs baseline: 4.8236x; 1.0230x over previous
#include <cuda_runtime.h>
#include <cuda_fp16.h>
#include <cstdint>

#define NJ 22
#define NF 8
#define SEQ 176
#define DM 256
#define HEADS 8
#define HD 32
#define BATCH 512
#define MROWS (BATCH*SEQ)   // 90112

typedef unsigned long long u64;

// Scratch: A=(x+pe) split fp16 hi/lo, W fp16, QKV fp16
__device__ __half g_Ah[(size_t)MROWS*DM];
__device__ __half g_Al[(size_t)MROWS*DM];
__device__ __half g_Wf[768*DM];
__device__ __half g_qkv[3ULL*(size_t)MROWS*(size_t)DM];

// ---------------------------------------------------------------------------
// helpers
// ---------------------------------------------------------------------------
__device__ __forceinline__ uint32_t smem_u32(const void* p){
    uint32_t a;
    asm("{ .reg .u64 t; cvta.to.shared.u64 t, %1; cvt.u32.u64 %0, t; }" : "=r"(a) : "l"(p));
    return a;
}
__device__ __forceinline__ uint32_t sw64(uint32_t off){ return off ^ ((off >> 3) & 0x30); }

__device__ __forceinline__ void cpasync16(uint32_t dst, const void* src){
    asm volatile("cp.async.cg.shared.global [%0], [%1], 16;" :: "r"(dst), "l"(src) : "memory");
}
#define CPASYNC_COMMIT() asm volatile("cp.async.commit_group;" ::: "memory")
#define CPASYNC_WAIT(n)  asm volatile("cp.async.wait_group %0;" :: "n"(n) : "memory")

#define LDSM_X4(r0,r1,r2,r3,addr) \
    asm volatile("ldmatrix.sync.aligned.m8n8.x4.shared.b16 {%0,%1,%2,%3}, [%4];" \
        : "=r"(r0),"=r"(r1),"=r"(r2),"=r"(r3) : "r"(addr))
#define MMAF16(d,a0,a1,a2,a3,b0,b1) \
    asm volatile("mma.sync.aligned.m16n8k16.row.col.f32.f16.f16.f32 " \
        "{%0,%1,%2,%3},{%4,%5,%6,%7},{%8,%9},{%0,%1,%2,%3};" \
        : "+f"((d)[0]),"+f"((d)[1]),"+f"((d)[2]),"+f"((d)[3]) \
        : "r"(a0),"r"(a1),"r"(a2),"r"(a3),"r"(b0),"r"(b1))

// fp32x4 -> packed fp16 hi (4) and lo (4)
__device__ __forceinline__ void split4h(float a, float b, float c, float d, u64& hi, u64& lo){
    __half ha = __float2half(a), hb = __float2half(b);
    __half hc = __float2half(c), hd = __float2half(d);
    __half la = __float2half(a - __half2float(ha));
    __half lb = __float2half(b - __half2float(hb));
    __half lc = __float2half(c - __half2float(hc));
    __half ld = __float2half(d - __half2float(hd));
    hi = (u64)__half_as_ushort(ha) | ((u64)__half_as_ushort(hb) << 16)
       | ((u64)__half_as_ushort(hc) << 32) | ((u64)__half_as_ushort(hd) << 48);
    lo = (u64)__half_as_ushort(la) | ((u64)__half_as_ushort(lb) << 16)
       | ((u64)__half_as_ushort(lc) << 32) | ((u64)__half_as_ushort(ld) << 48);
}

// fp32x2 packed FMA (attention kernel)
__device__ __forceinline__ u64 pack2(float x, float y){
    u64 r; asm("mov.b64 %0, {%1,%2};" : "=l"(r) : "f"(x), "f"(y)); return r;
}
__device__ __forceinline__ float2 unpack2(u64 v){
    float2 f; asm("mov.b64 {%0,%1}, %2;" : "=f"(f.x), "=f"(f.y) : "l"(v)); return f;
}
__device__ __forceinline__ u64 ffma2(u64 a, u64 b, u64 c){
    u64 d; asm("fma.rn.f32x2 %0, %1, %2, %3;" : "=l"(d) : "l"(a), "l"(b), "l"(c)); return d;
}

// ---------------------------------------------------------------------------
// Fused prep: W -> fp16, and (x + PE) -> fp16 hi/lo split (PE inline).
// idx < WN4        : weight float4s
// idx >= WN4       : A float4s
// ---------------------------------------------------------------------------
#define WN4 (768*DM/4)                 // 49152
#define AN4 (MROWS*DM/4)               // 5767168
#define PREP_BLOCKS ((WN4 + AN4)/256)  // 22720 exactly

__global__ __launch_bounds__(256) void prep_kernel(
    const float* __restrict__ x,
    const float* __restrict__ wq, const float* __restrict__ wk, const float* __restrict__ wv)
{
    int idx = blockIdx.x * 256 + threadIdx.x;
    if (idx < WN4) {
        int row = idx >> 6;
        const float* w = (row < 256) ? wq : (row < 512) ? wk : wv;
        int lrow = row & 255;
        int c4   = idx & 63;
        float4 v = *(const float4*)(w + (size_t)lrow*DM + c4*4);
        u64 hv = (u64)__half_as_ushort(__float2half(v.x))
               | ((u64)__half_as_ushort(__float2half(v.y)) << 16)
               | ((u64)__half_as_ushort(__float2half(v.z)) << 32)
               | ((u64)__half_as_ushort(__float2half(v.w)) << 48);
        *(u64*)(g_Wf + (size_t)idx*4) = hv;
    } else {
        int e4 = idx - WN4;
        int m  = e4 >> 6;
        int c4 = e4 & 63;
        float4 xa = *(const float4*)(x + (size_t)m*DM + c4*4);
        // PE (spatial): pos = joint id = m % 22; dims d0 = c4*4 .. +3
        const float j = (float)(m % NJ);
        const float NEGLOG = -0.035977892078032f;   // -ln(10000)/256
        float e0 = __expf(NEGLOG * (float)(c4*4));
        float e1 = __expf(NEGLOG * (float)(c4*4 + 2));
        float s0, c0, s1, c1;
        __sincosf(j*e0, &s0, &c0);
        __sincosf(j*e1, &s1, &c1);
        u64 hi, lo;
        split4h(xa.x + s0, xa.y + c0, xa.z + s1, xa.w + c1, hi, lo);
        *(u64*)(g_Ah + (size_t)e4*4) = hi;
        *(u64*)(g_Al + (size_t)e4*4) = lo;
    }
}

// ---------------------------------------------------------------------------
// QKV GEMM: fp16 2-term mma.sync (A split hi/lo, B single fp16).
// CTA tile 128x128. KC=32, 3-stage cp.async pipeline, 1 syncthreads/chunk.
// Output stored as fp16.  (unchanged from best-known)
// ---------------------------------------------------------------------------
#define MT 128
#define NT 128
#define KC 32
#define NCHUNK (DM/KC)                 // 8
#define ARR8K 8192                     // 128 rows x 32 fp16
#define STAGE (3*ARR8K)                // Ah, Al, Bf = 24 KB
#define NSTAGE 3
#define GEMM_SMEM (NSTAGE*STAGE + 1024)

__device__ __forceinline__ void gemm_load_chunk(uint32_t uS, int m0, int n0,
                                                int cc, int ss, int tid)
{
    const uint32_t sb = uS + ss*STAGE;
#pragma unroll
    for (int j = 0; j < 6; j++) {
        int idx = j*256 + tid;         // 0..1535
        int arr = idx >> 9;            // 0=Ah 1=Al 2=Bf
        int w   = idx & 511;
        int r   = w >> 2;              // row 0..127
        int seg = w & 3;               // 16B segment
        uint32_t off = sw64((uint32_t)(r*64 + seg*16)) + arr*ARR8K;
        if (arr == 0) {
            cpasync16(sb + off, g_Ah + (size_t)(m0 + r)*DM + cc*KC + seg*8);
        } else if (arr == 1) {
            cpasync16(sb + off, g_Al + (size_t)(m0 + r)*DM + cc*KC + seg*8);
        } else {
            cpasync16(sb + off, g_Wf + (size_t)(n0 + r)*DM + cc*KC + seg*8);
        }
    }
}

__global__ __launch_bounds__(256, 2) void qkv_mma_kernel(
    const float* __restrict__ bq, const float* __restrict__ bk, const float* __restrict__ bv)
{
    extern __shared__ char dyn_raw[];
    char* dsm = (char*)(((uintptr_t)dyn_raw + 1023) & ~(uintptr_t)1023);
    const uint32_t uS = smem_u32(dsm);

    const int tid  = threadIdx.x;
    const int wid  = tid >> 5;
    const int lane = tid & 31;
    const int wm   = wid & 3;              // 4 m-warps x 32 rows
    const int wn   = wid >> 2;             // 2 n-warps x 64 cols

    const int n0    = blockIdx.x * NT;     // 0..640 (global weight-row base)
    const int m0    = blockIdx.y * MT;
    const int which = n0 >> 8;             // 0=Q 1=K 2=V
    const int ncol0 = n0 & 255;
    const float* bbase = (which == 0) ? bq : (which == 1) ? bk : bv;

    // ldmatrix per-lane source coordinates (64B rows)
    const int a_row = wm*32 + (lane & 15);
    const int a_kb  = (lane >> 4) * 16;
    const int b_row = wn*64 + (lane & 7) + ((lane >> 4) & 1)*8;
    const int b_kb  = ((lane >> 3) & 1) * 16;

    float acc[2][8][4];
#pragma unroll
    for (int i = 0; i < 2; i++)
#pragma unroll
        for (int j = 0; j < 8; j++)
#pragma unroll
            for (int q = 0; q < 4; q++) acc[i][j][q] = 0.f;

    // prologue: 2 chunks in flight
    gemm_load_chunk(uS, m0, n0, 0, 0, tid);
    CPASYNC_COMMIT();
    gemm_load_chunk(uS, m0, n0, 1, 1, tid);
    CPASYNC_COMMIT();

    for (int c = 0; c < NCHUNK; c++) {
        if (c + 2 < NCHUNK) {
            CPASYNC_WAIT(1);               // chunk c landed
            __syncthreads();               // publish c; stage (c+2)%3 free
            gemm_load_chunk(uS, m0, n0, c + 2, (c + 2) % NSTAGE, tid);
            CPASYNC_COMMIT();
        } else if (c + 1 < NCHUNK) {
            CPASYNC_WAIT(1);
            __syncthreads();
        } else {
            CPASYNC_WAIT(0);
            __syncthreads();
        }

        const uint32_t uAh = uS + (c % NSTAGE)*STAGE;
        const uint32_t uAl = uAh + ARR8K;
        const uint32_t uBf = uAh + 2*ARR8K;

#pragma unroll
        for (int k = 0; k < 2; k++) {
            const int kb = k*32;   // bytes
            uint32_t ao0 = sw64((uint32_t)( a_row      *64 + kb + a_kb));
            uint32_t ao1 = sw64((uint32_t)((a_row + 16)*64 + kb + a_kb));
            uint32_t ah0[4], ah1[4], al0[4], al1[4];
            LDSM_X4(ah0[0],ah0[1],ah0[2],ah0[3], uAh + ao0);
            LDSM_X4(ah1[0],ah1[1],ah1[2],ah1[3], uAh + ao1);
            LDSM_X4(al0[0],al0[1],al0[2],al0[3], uAl + ao0);
            LDSM_X4(al1[0],al1[1],al1[2],al1[3], uAl + ao1);
#pragma unroll
            for (int nt2 = 0; nt2 < 4; nt2++) {
                uint32_t bo = sw64((uint32_t)((b_row + nt2*16)*64 + kb + b_kb));
                uint32_t bf[4];
                LDSM_X4(bf[0], bf[1], bf[2], bf[3], uBf + bo);
                const int nt = nt2*2;
                // same-acc MMAs spaced by 4 independent ones
                MMAF16(acc[0][nt  ], ah0[0],ah0[1],ah0[2],ah0[3], bf[0],bf[1]);
                MMAF16(acc[1][nt  ], ah1[0],ah1[1],ah1[2],ah1[3], bf[0],bf[1]);
                MMAF16(acc[0][nt+1], ah0[0],ah0[1],ah0[2],ah0[3], bf[2],bf[3]);
                MMAF16(acc[1][nt+1], ah1[0],ah1[1],ah1[2],ah1[3], bf[2],bf[3]);
                MMAF16(acc[0][nt  ], al0[0],al0[1],al0[2],al0[3], bf[0],bf[1]);
                MMAF16(acc[1][nt  ], al1[0],al1[1],al1[2],al1[3], bf[0],bf[1]);
                MMAF16(acc[0][nt+1], al0[0],al0[1],al0[2],al0[3], bf[2],bf[3]);
                MMAF16(acc[1][nt+1], al1[0],al1[1],al1[2],al1[3], bf[2],bf[3]);
            }
        }
    }

    // ---- epilogue: bias add + fp16 stores ----
    __half* obase = g_qkv + (size_t)which*MROWS*DM;
    const int mr = m0 + wm*32 + (lane >> 2);
    const int nc = ncol0 + wn*64 + (lane & 3)*2;
#pragma unroll
    for (int mt = 0; mt < 2; mt++) {
#pragma unroll
        for (int nt = 0; nt < 8; nt++) {
            const int col = nc + nt*8;
            const float b0 = bbase[col], b1 = bbase[col+1];
            __half2 h0 = __floats2half2_rn(acc[mt][nt][0] + b0, acc[mt][nt][1] + b1);
            __half2 h1 = __floats2half2_rn(acc[mt][nt][2] + b0, acc[mt][nt][3] + b1);
            *(__half2*)(obase + (size_t)(mr + mt*16    )*DM + col) = h0;
            *(__half2*)(obase + (size_t)(mr + mt*16 + 8)*DM + col) = h1;
        }
    }
}

// ---------------------------------------------------------------------------
// Frame-local attention: block = (batch, frame), warp = head.
// K/V staged fp32; Q/O staged fp16 (stride-34 rows: 17-word stride, coprime
// with 32 banks -> conflict-free per-lane row access). 55.7 KB -> 4 CTAs/SM.
// ---------------------------------------------------------------------------
#define ATT_KV   (HEADS*NJ*HD)                 // floats per K or V stage
#define QO_STRIDE 34
#define ATT_QO_H (HEADS*NJ*QO_STRIDE)          // halves
#define ATT_SMEM (2*ATT_KV*4 + ATT_QO_H*2)     // 45056 + 11968 = 57024 B

__global__ __launch_bounds__(256) void attention_kernel(float* __restrict__ out)
{
    extern __shared__ char smraw[];
    float*  ksb  = (float*)smraw;
    float*  vsb  = ksb + ATT_KV;
    __half* qsb  = (__half*)(vsb + ATT_KV);

    const int bf   = blockIdx.x;
    const int b    = bf >> 3;
    const int f    = bf & 7;
    const int h    = threadIdx.x >> 5;
    const int lane = threadIdx.x & 31;

    float*  ksh = ksb + h*NJ*HD;
    float*  vsh = vsb + h*NJ*HD;
    __half* qsh = qsb + h*NJ*QO_STRIDE;

    const size_t row0 = (size_t)b * SEQ + (size_t)f * NJ;
    const __half* Q = g_qkv;
    const __half* K = g_qkv + (size_t)MROWS * DM;
    const __half* V = g_qkv + 2ULL * (size_t)MROWS * DM;

    // Stage: lane = dim, loop joints (coalesced)
#pragma unroll
    for (int kj = 0; kj < NJ; kj++) {
        const size_t src = (row0 + kj) * DM + h * HD + lane;
        ksh[kj*HD + lane] = __half2float(K[src]);
        vsh[kj*HD + lane] = __half2float(V[src]);
        qsh[kj*QO_STRIDE + lane] = Q[src];        // raw fp16 copy
    }
    __syncwarp();

    // Per-lane query row from fp16 smem (half2-aligned: even stride)
    const int qi = (lane < NJ) ? lane : (NJ - 1);
    u64 q2[16];
#pragma unroll
    for (int i = 0; i < 16; i++) {
        __half2 hq = *(const __half2*)(qsh + qi*QO_STRIDE + 2*i);
        float2 fq = __half22float2(hq);
        q2[i] = pack2(fq.x, fq.y);
    }
    __syncwarp();   // Q consumed before O overwrites the tile

    const u64* ksp = (const u64*)ksh;
    float sc[NJ];
#pragma unroll
    for (int kj = 0; kj < NJ; kj++) {
        u64 acc = 0ULL;
#pragma unroll
        for (int d = 0; d < 16; d++) acc = ffma2(q2[d], ksp[kj*16 + d], acc);
        float2 s = unpack2(acc);
        sc[kj] = (s.x + s.y) * 0.17677669529663687f;   // 1/sqrt(32)
    }

    float m = sc[0];
#pragma unroll
    for (int kj = 1; kj < NJ; kj++) m = fmaxf(m, sc[kj]);
    float sum = 0.f;
#pragma unroll
    for (int kj = 0; kj < NJ; kj++) { sc[kj] = __expf(sc[kj] - m); sum += sc[kj]; }
    const float inv = 1.0f / sum;

    const u64* vsp = (const u64*)vsh;
    u64 o2[16];
#pragma unroll
    for (int i = 0; i < 16; i++) o2[i] = 0ULL;
#pragma unroll
    for (int kj = 0; kj < NJ; kj++) {
        float p = sc[kj] * inv;
        u64 pp = pack2(p, p);
#pragma unroll
        for (int d = 0; d < 16; d++) o2[d] = ffma2(pp, vsp[kj*16 + d], o2[d]);
    }

    // Stage O (fp16) into the reused Q tile, then store coalesced as fp32
    if (lane < NJ) {
#pragma unroll
        for (int i = 0; i < 16; i++) {
            float2 s = unpack2(o2[i]);
            *(__half2*)(qsh + qi*QO_STRIDE + 2*i) = __floats2half2_rn(s.x, s.y);
        }
    }
    __syncwarp();
#pragma unroll
    for (int kj = 0; kj < NJ; kj++)
        out[(row0 + kj) * DM + h * HD + lane] = __half2float(qsh[kj*QO_STRIDE + lane]);
}

// ---------------------------------------------------------------------------
extern "C" void kernel_launch(void* const* d_in, const int* in_sizes, int n_in,
                              void* d_out, int out_size)
{
    const float* x  = (const float*)d_in[0];
    const float* wq = (const float*)d_in[1];
    const float* bq = (const float*)d_in[2];
    const float* wk = (const float*)d_in[3];
    const float* bk = (const float*)d_in[4];
    const float* wv = (const float*)d_in[5];
    const float* bv = (const float*)d_in[6];
    float* out = (float*)d_out;

    cudaFuncSetAttribute(qkv_mma_kernel, cudaFuncAttributeMaxDynamicSharedMemorySize, GEMM_SMEM);
    cudaFuncSetAttribute(attention_kernel, cudaFuncAttributeMaxDynamicSharedMemorySize, ATT_SMEM);

    prep_kernel<<<PREP_BLOCKS, 256>>>(x, wq, wk, wv);

    dim3 ggrid(768 / NT, MROWS / MT);   // (6, 704); x-fastest shares A tile in L2
    qkv_mma_kernel<<<ggrid, 256, GEMM_SMEM>>>(bq, bk, bv);

    attention_kernel<<<BATCH * NF, 256, ATT_SMEM>>>(out);
}

// round 13
// speedup vs baseline: 5.9243x; 1.2282x over previous
#include <cuda_runtime.h>
#include <cuda_fp16.h>
#include <cstdint>

#define NJ 22
#define NF 8
#define SEQ 176
#define DM 256
#define HEADS 8
#define HD 32
#define BATCH 512
#define MROWS (BATCH*SEQ)   // 90112

typedef unsigned long long u64;

// Scratch: A=(x+pe) split fp16 hi/lo, W fp16, QKV fp16
__device__ __half g_Ah[(size_t)MROWS*DM];
__device__ __half g_Al[(size_t)MROWS*DM];
__device__ __half g_Wf[768*DM];
__device__ __half g_qkv[3ULL*(size_t)MROWS*(size_t)DM];

// ---------------------------------------------------------------------------
// helpers
// ---------------------------------------------------------------------------
__device__ __forceinline__ uint32_t smem_u32(const void* p){
    uint32_t a;
    asm("{ .reg .u64 t; cvta.to.shared.u64 t, %1; cvt.u32.u64 %0, t; }" : "=r"(a) : "l"(p));
    return a;
}
__device__ __forceinline__ uint32_t sw64(uint32_t off){ return off ^ ((off >> 3) & 0x30); }

__device__ __forceinline__ void cpasync16(uint32_t dst, const void* src){
    asm volatile("cp.async.cg.shared.global [%0], [%1], 16;" :: "r"(dst), "l"(src) : "memory");
}
#define CPASYNC_COMMIT() asm volatile("cp.async.commit_group;" ::: "memory")
#define CPASYNC_WAIT(n)  asm volatile("cp.async.wait_group %0;" :: "n"(n) : "memory")

#define LDSM_X4(r0,r1,r2,r3,addr) \
    asm volatile("ldmatrix.sync.aligned.m8n8.x4.shared.b16 {%0,%1,%2,%3}, [%4];" \
        : "=r"(r0),"=r"(r1),"=r"(r2),"=r"(r3) : "r"(addr))
#define LDSM_X4_T(r0,r1,r2,r3,addr) \
    asm volatile("ldmatrix.sync.aligned.m8n8.x4.trans.shared.b16 {%0,%1,%2,%3}, [%4];" \
        : "=r"(r0),"=r"(r1),"=r"(r2),"=r"(r3) : "r"(addr))
#define MMAF16(d,a0,a1,a2,a3,b0,b1) \
    asm volatile("mma.sync.aligned.m16n8k16.row.col.f32.f16.f16.f32 " \
        "{%0,%1,%2,%3},{%4,%5,%6,%7},{%8,%9},{%0,%1,%2,%3};" \
        : "+f"((d)[0]),"+f"((d)[1]),"+f"((d)[2]),"+f"((d)[3]) \
        : "r"(a0),"r"(a1),"r"(a2),"r"(a3),"r"(b0),"r"(b1))

// fp32x4 -> packed fp16 hi (4) and lo (4)
__device__ __forceinline__ void split4h(float a, float b, float c, float d, u64& hi, u64& lo){
    __half ha = __float2half(a), hb = __float2half(b);
    __half hc = __float2half(c), hd = __float2half(d);
    __half la = __float2half(a - __half2float(ha));
    __half lb = __float2half(b - __half2float(hb));
    __half lc = __float2half(c - __half2float(hc));
    __half ld = __float2half(d - __half2float(hd));
    hi = (u64)__half_as_ushort(ha) | ((u64)__half_as_ushort(hb) << 16)
       | ((u64)__half_as_ushort(hc) << 32) | ((u64)__half_as_ushort(hd) << 48);
    lo = (u64)__half_as_ushort(la) | ((u64)__half_as_ushort(lb) << 16)
       | ((u64)__half_as_ushort(lc) << 32) | ((u64)__half_as_ushort(ld) << 48);
}

__device__ __forceinline__ uint32_t f22u(float x, float y){
    __half2 t = __floats2half2_rn(x, y);
    return *(uint32_t*)&t;
}

// ---------------------------------------------------------------------------
// Fused prep: W -> fp16, and (x + PE) -> fp16 hi/lo split (PE inline).
// ---------------------------------------------------------------------------
#define WN4 (768*DM/4)                 // 49152
#define AN4 (MROWS*DM/4)               // 5767168
#define PREP_BLOCKS ((WN4 + AN4)/256)  // 22720 exactly

__global__ __launch_bounds__(256) void prep_kernel(
    const float* __restrict__ x,
    const float* __restrict__ wq, const float* __restrict__ wk, const float* __restrict__ wv)
{
    int idx = blockIdx.x * 256 + threadIdx.x;
    if (idx < WN4) {
        int row = idx >> 6;
        const float* w = (row < 256) ? wq : (row < 512) ? wk : wv;
        int lrow = row & 255;
        int c4   = idx & 63;
        float4 v = *(const float4*)(w + (size_t)lrow*DM + c4*4);
        u64 hv = (u64)__half_as_ushort(__float2half(v.x))
               | ((u64)__half_as_ushort(__float2half(v.y)) << 16)
               | ((u64)__half_as_ushort(__float2half(v.z)) << 32)
               | ((u64)__half_as_ushort(__float2half(v.w)) << 48);
        *(u64*)(g_Wf + (size_t)idx*4) = hv;
    } else {
        int e4 = idx - WN4;
        int m  = e4 >> 6;
        int c4 = e4 & 63;
        float4 xa = *(const float4*)(x + (size_t)m*DM + c4*4);
        const float j = (float)(m % NJ);
        const float NEGLOG = -0.035977892078032f;   // -ln(10000)/256
        float e0 = __expf(NEGLOG * (float)(c4*4));
        float e1 = __expf(NEGLOG * (float)(c4*4 + 2));
        float s0, c0, s1, c1;
        __sincosf(j*e0, &s0, &c0);
        __sincosf(j*e1, &s1, &c1);
        u64 hi, lo;
        split4h(xa.x + s0, xa.y + c0, xa.z + s1, xa.w + c1, hi, lo);
        *(u64*)(g_Ah + (size_t)e4*4) = hi;
        *(u64*)(g_Al + (size_t)e4*4) = lo;
    }
}

// ---------------------------------------------------------------------------
// QKV GEMM: fp16 2-term mma.sync (A split hi/lo, B single fp16).
// CTA tile 128x128. KC=32, 3-stage cp.async pipeline. (unchanged best-known)
// ---------------------------------------------------------------------------
#define MT 128
#define NT 128
#define KC 32
#define NCHUNK (DM/KC)                 // 8
#define ARR8K 8192                     // 128 rows x 32 fp16
#define STAGE (3*ARR8K)                // Ah, Al, Bf = 24 KB
#define NSTAGE 3
#define GEMM_SMEM (NSTAGE*STAGE + 1024)

__device__ __forceinline__ void gemm_load_chunk(uint32_t uS, int m0, int n0,
                                                int cc, int ss, int tid)
{
    const uint32_t sb = uS + ss*STAGE;
#pragma unroll
    for (int j = 0; j < 6; j++) {
        int idx = j*256 + tid;         // 0..1535
        int arr = idx >> 9;            // 0=Ah 1=Al 2=Bf
        int w   = idx & 511;
        int r   = w >> 2;              // row 0..127
        int seg = w & 3;               // 16B segment
        uint32_t off = sw64((uint32_t)(r*64 + seg*16)) + arr*ARR8K;
        if (arr == 0) {
            cpasync16(sb + off, g_Ah + (size_t)(m0 + r)*DM + cc*KC + seg*8);
        } else if (arr == 1) {
            cpasync16(sb + off, g_Al + (size_t)(m0 + r)*DM + cc*KC + seg*8);
        } else {
            cpasync16(sb + off, g_Wf + (size_t)(n0 + r)*DM + cc*KC + seg*8);
        }
    }
}

__global__ __launch_bounds__(256, 2) void qkv_mma_kernel(
    const float* __restrict__ bq, const float* __restrict__ bk, const float* __restrict__ bv)
{
    extern __shared__ char dyn_raw[];
    char* dsm = (char*)(((uintptr_t)dyn_raw + 1023) & ~(uintptr_t)1023);
    const uint32_t uS = smem_u32(dsm);

    const int tid  = threadIdx.x;
    const int wid  = tid >> 5;
    const int lane = tid & 31;
    const int wm   = wid & 3;
    const int wn   = wid >> 2;

    const int n0    = blockIdx.x * NT;
    const int m0    = blockIdx.y * MT;
    const int which = n0 >> 8;
    const int ncol0 = n0 & 255;
    const float* bbase = (which == 0) ? bq : (which == 1) ? bk : bv;

    const int a_row = wm*32 + (lane & 15);
    const int a_kb  = (lane >> 4) * 16;
    const int b_row = wn*64 + (lane & 7) + ((lane >> 4) & 1)*8;
    const int b_kb  = ((lane >> 3) & 1) * 16;

    float acc[2][8][4];
#pragma unroll
    for (int i = 0; i < 2; i++)
#pragma unroll
        for (int j = 0; j < 8; j++)
#pragma unroll
            for (int q = 0; q < 4; q++) acc[i][j][q] = 0.f;

    gemm_load_chunk(uS, m0, n0, 0, 0, tid);
    CPASYNC_COMMIT();
    gemm_load_chunk(uS, m0, n0, 1, 1, tid);
    CPASYNC_COMMIT();

    for (int c = 0; c < NCHUNK; c++) {
        if (c + 2 < NCHUNK) {
            CPASYNC_WAIT(1);
            __syncthreads();
            gemm_load_chunk(uS, m0, n0, c + 2, (c + 2) % NSTAGE, tid);
            CPASYNC_COMMIT();
        } else if (c + 1 < NCHUNK) {
            CPASYNC_WAIT(1);
            __syncthreads();
        } else {
            CPASYNC_WAIT(0);
            __syncthreads();
        }

        const uint32_t uAh = uS + (c % NSTAGE)*STAGE;
        const uint32_t uAl = uAh + ARR8K;
        const uint32_t uBf = uAh + 2*ARR8K;

#pragma unroll
        for (int k = 0; k < 2; k++) {
            const int kb = k*32;
            uint32_t ao0 = sw64((uint32_t)( a_row      *64 + kb + a_kb));
            uint32_t ao1 = sw64((uint32_t)((a_row + 16)*64 + kb + a_kb));
            uint32_t ah0[4], ah1[4], al0[4], al1[4];
            LDSM_X4(ah0[0],ah0[1],ah0[2],ah0[3], uAh + ao0);
            LDSM_X4(ah1[0],ah1[1],ah1[2],ah1[3], uAh + ao1);
            LDSM_X4(al0[0],al0[1],al0[2],al0[3], uAl + ao0);
            LDSM_X4(al1[0],al1[1],al1[2],al1[3], uAl + ao1);
#pragma unroll
            for (int nt2 = 0; nt2 < 4; nt2++) {
                uint32_t bo = sw64((uint32_t)((b_row + nt2*16)*64 + kb + b_kb));
                uint32_t bf[4];
                LDSM_X4(bf[0], bf[1], bf[2], bf[3], uBf + bo);
                const int nt = nt2*2;
                MMAF16(acc[0][nt  ], ah0[0],ah0[1],ah0[2],ah0[3], bf[0],bf[1]);
                MMAF16(acc[1][nt  ], ah1[0],ah1[1],ah1[2],ah1[3], bf[0],bf[1]);
                MMAF16(acc[0][nt+1], ah0[0],ah0[1],ah0[2],ah0[3], bf[2],bf[3]);
                MMAF16(acc[1][nt+1], ah1[0],ah1[1],ah1[2],ah1[3], bf[2],bf[3]);
                MMAF16(acc[0][nt  ], al0[0],al0[1],al0[2],al0[3], bf[0],bf[1]);
                MMAF16(acc[1][nt  ], al1[0],al1[1],al1[2],al1[3], bf[0],bf[1]);
                MMAF16(acc[0][nt+1], al0[0],al0[1],al0[2],al0[3], bf[2],bf[3]);
                MMAF16(acc[1][nt+1], al1[0],al1[1],al1[2],al1[3], bf[2],bf[3]);
            }
        }
    }

    __half* obase = g_qkv + (size_t)which*MROWS*DM;
    const int mr = m0 + wm*32 + (lane >> 2);
    const int nc = ncol0 + wn*64 + (lane & 3)*2;
#pragma unroll
    for (int mt = 0; mt < 2; mt++) {
#pragma unroll
        for (int nt = 0; nt < 8; nt++) {
            const int col = nc + nt*8;
            const float b0 = bbase[col], b1 = bbase[col+1];
            __half2 h0 = __floats2half2_rn(acc[mt][nt][0] + b0, acc[mt][nt][1] + b1);
            __half2 h1 = __floats2half2_rn(acc[mt][nt][2] + b0, acc[mt][nt][3] + b1);
            *(__half2*)(obase + (size_t)(mr + mt*16    )*DM + col) = h0;
            *(__half2*)(obase + (size_t)(mr + mt*16 + 8)*DM + col) = h1;
        }
    }
}

// ---------------------------------------------------------------------------
// Tensor-core frame-local attention. Block = (batch, frame), warp = head.
// S = Q@K^T (12 MMAs, M=32 pad, N=24, K=32) -> fragment softmax (shfl.bfly
// within 4-lane column groups) -> P fragments reuse S accum layout -> P@V
// (16 MMAs, V^T fragments via ldmatrix.trans from a stride-72 smem tile).
// Q/K fragments load directly from gmem. O staged fp16 -> coalesced stores.
// ---------------------------------------------------------------------------
#define VT_STRIDE 72   // halves; 144B rows: 16B-aligned, 8-row bank-distinct
#define OS_STRIDE 34   // halves; 17-word rows, conflict-free
#define ATT_SMEM ((HEADS*32*VT_STRIDE + HEADS*32*OS_STRIDE)*2)   // 54272 B

__global__ __launch_bounds__(256, 2) void attention_kernel(float* __restrict__ out)
{
    extern __shared__ __half smh[];
    const int bf   = blockIdx.x;
    const int b    = bf >> 3;
    const int f    = bf & 7;
    const int h    = threadIdx.x >> 5;
    const int lane = threadIdx.x & 31;
    const int g    = lane >> 2;          // fragment row group
    const int c    = lane & 3;           // fragment col group

    __half* vt = smh + h*(32*VT_STRIDE);
    __half* os = smh + HEADS*(32*VT_STRIDE) + h*(32*OS_STRIDE);

    const size_t row0 = (size_t)b * SEQ + (size_t)f * NJ;
    const __half* Qb = g_qkv + row0*DM + h*HD;
    const __half* Kb = g_qkv + (size_t)MROWS*DM + row0*DM + h*HD;
    const __half* Vb = g_qkv + 2ULL*(size_t)MROWS*DM + row0*DM + h*HD;

    // ---- stage V (fp16), zero pad rows 22-31 (0*inf=NaN guard) ----
#pragma unroll
    for (int kj = 0; kj < NJ; kj++)
        vt[kj*VT_STRIDE + lane] = Vb[(size_t)kj*DM + lane];
#pragma unroll
    for (int r = NJ; r < 32; r++)
        vt[r*VT_STRIDE + lane] = __ushort_as_half(0);
    __syncwarp();

    // ---- K B-fragments direct from gmem: kb[n][kk][2]
    // b0 = {K[n*8+g][2c + kk*16], +1}, b1 = +8 dims ----
    uint32_t kb[3][2][2];
#pragma unroll
    for (int n = 0; n < 3; n++)
#pragma unroll
        for (int kk = 0; kk < 2; kk++) {
            const __half* p = Kb + (size_t)(n*8 + g)*DM + kk*16 + 2*c;
            kb[n][kk][0] = *(const uint32_t*)p;
            kb[n][kk][1] = *(const uint32_t*)(p + 8);
        }

    // ---- V^T B-fragments via ldmatrix.trans: vb[n(dims/8)][kk(keys/16)][2] ----
    uint32_t vb[4][2][2];
    {
        const uint32_t vtb = smem_u32(vt);
        const int vrow = (lane & 7) + ((lane >> 3) & 1)*8;
        const int vcol = (lane >> 4)*8;
#pragma unroll
        for (int np = 0; np < 2; np++)
#pragma unroll
            for (int kk = 0; kk < 2; kk++) {
                uint32_t addr = vtb + (uint32_t)((kk*16 + vrow)*VT_STRIDE + np*16 + vcol)*2;
                LDSM_X4_T(vb[2*np][kk][0], vb[2*np][kk][1],
                          vb[2*np+1][kk][0], vb[2*np+1][kk][1], addr);
            }
    }

    const uint32_t zero2 = 0;
    const float SC = 0.17677669529663687f;   // 1/sqrt(32)

#pragma unroll
    for (int m = 0; m < 2; m++) {
        // Q A-fragments direct from gmem (rows m*16+g, m*16+g+8)
        uint32_t qa[2][4];
#pragma unroll
        for (int kk = 0; kk < 2; kk++) {
            const __half* p = Qb + (size_t)(m*16 + g)*DM + kk*16 + 2*c;
            qa[kk][0] = *(const uint32_t*)p;
            qa[kk][1] = *(const uint32_t*)(p + 8*DM);
            qa[kk][2] = *(const uint32_t*)(p + 8);
            qa[kk][3] = *(const uint32_t*)(p + 8*DM + 8);
        }

        // S = Q@K^T
        float s[3][4];
#pragma unroll
        for (int n = 0; n < 3; n++) {
            s[n][0] = s[n][1] = s[n][2] = s[n][3] = 0.f;
#pragma unroll
            for (int kk = 0; kk < 2; kk++)
                MMAF16(s[n], qa[kk][0],qa[kk][1],qa[kk][2],qa[kk][3],
                       kb[n][kk][0], kb[n][kk][1]);
        }
        // scale + mask cols >= 22 (frag n=2, c=3 -> cols 22,23)
#pragma unroll
        for (int n = 0; n < 3; n++)
#pragma unroll
            for (int j = 0; j < 4; j++) s[n][j] *= SC;
        if (c == 3) { s[2][0] = s[2][1] = s[2][2] = s[2][3] = -1e30f; }

        // row max (row g -> [0],[1]; row g+8 -> [2],[3]) via 4-lane bfly
        float mxa = fmaxf(fmaxf(s[0][0], s[0][1]),
                    fmaxf(fmaxf(s[1][0], s[1][1]), fmaxf(s[2][0], s[2][1])));
        float mxb = fmaxf(fmaxf(s[0][2], s[0][3]),
                    fmaxf(fmaxf(s[1][2], s[1][3]), fmaxf(s[2][2], s[2][3])));
        mxa = fmaxf(mxa, __shfl_xor_sync(0xffffffffu, mxa, 1));
        mxa = fmaxf(mxa, __shfl_xor_sync(0xffffffffu, mxa, 2));
        mxb = fmaxf(mxb, __shfl_xor_sync(0xffffffffu, mxb, 1));
        mxb = fmaxf(mxb, __shfl_xor_sync(0xffffffffu, mxb, 2));

        float p[3][4];
        float sa = 0.f, sb = 0.f;
#pragma unroll
        for (int n = 0; n < 3; n++) {
            p[n][0] = __expf(s[n][0] - mxa);
            p[n][1] = __expf(s[n][1] - mxa);
            p[n][2] = __expf(s[n][2] - mxb);
            p[n][3] = __expf(s[n][3] - mxb);
            sa += p[n][0] + p[n][1];
            sb += p[n][2] + p[n][3];
        }
        sa += __shfl_xor_sync(0xffffffffu, sa, 1);
        sa += __shfl_xor_sync(0xffffffffu, sa, 2);
        sb += __shfl_xor_sync(0xffffffffu, sb, 1);
        sb += __shfl_xor_sync(0xffffffffu, sb, 2);
        const float inva = 1.f / sa;
        const float invb = 1.f / sb;

        // P fragments: C(m16n8) layout == A(m16k16) layout, 2 n-frags per k16
        uint32_t pa0[4], pa1[2];
        pa0[0] = f22u(p[0][0], p[0][1]);   // row g,   keys 2c,2c+1
        pa0[1] = f22u(p[0][2], p[0][3]);   // row g+8
        pa0[2] = f22u(p[1][0], p[1][1]);   // row g,   keys 2c+8
        pa0[3] = f22u(p[1][2], p[1][3]);
        pa1[0] = f22u(p[2][0], p[2][1]);   // row g,   keys 2c+16
        pa1[1] = f22u(p[2][2], p[2][3]);

        // O = P@V
        float o[4][4];
#pragma unroll
        for (int n = 0; n < 4; n++) {
            o[n][0] = o[n][1] = o[n][2] = o[n][3] = 0.f;
            MMAF16(o[n], pa0[0], pa0[1], pa0[2], pa0[3], vb[n][0][0], vb[n][0][1]);
            MMAF16(o[n], pa1[0], pa1[1], zero2,  zero2,  vb[n][1][0], vb[n][1][1]);
        }

        // normalize + stage fp16
        const int ra = m*16 + g, rb = ra + 8;
#pragma unroll
        for (int n = 0; n < 4; n++) {
            *(__half2*)(os + ra*OS_STRIDE + 8*n + 2*c) = __floats2half2_rn(o[n][0]*inva, o[n][1]*inva);
            *(__half2*)(os + rb*OS_STRIDE + 8*n + 2*c) = __floats2half2_rn(o[n][2]*invb, o[n][3]*invb);
        }
    }
    __syncwarp();

    // coalesced output
#pragma unroll
    for (int kj = 0; kj < NJ; kj++)
        out[(row0 + kj)*DM + h*HD + lane] = __half2float(os[kj*OS_STRIDE + lane]);
}

// ---------------------------------------------------------------------------
extern "C" void kernel_launch(void* const* d_in, const int* in_sizes, int n_in,
                              void* d_out, int out_size)
{
    const float* x  = (const float*)d_in[0];
    const float* wq = (const float*)d_in[1];
    const float* bq = (const float*)d_in[2];
    const float* wk = (const float*)d_in[3];
    const float* bk = (const float*)d_in[4];
    const float* wv = (const float*)d_in[5];
    const float* bv = (const float*)d_in[6];
    float* out = (float*)d_out;

    cudaFuncSetAttribute(qkv_mma_kernel, cudaFuncAttributeMaxDynamicSharedMemorySize, GEMM_SMEM);
    cudaFuncSetAttribute(attention_kernel, cudaFuncAttributeMaxDynamicSharedMemorySize, ATT_SMEM);

    prep_kernel<<<PREP_BLOCKS, 256>>>(x, wq, wk, wv);

    dim3 ggrid(768 / NT, MROWS / MT);   // (6, 704); x-fastest shares A tile in L2
    qkv_mma_kernel<<<ggrid, 256, GEMM_SMEM>>>(bq, bk, bv);

    attention_kernel<<<BATCH * NF, 256, ATT_SMEM>>>(out);
}

// round 14
// speedup vs baseline: 7.7235x; 1.3037x over previous
#include <cuda_runtime.h>
#include <cuda_fp16.h>
#include <cstdint>

#define NJ 22
#define NF 8
#define SEQ 176
#define DM 256
#define HEADS 8
#define HD 32
#define BATCH 512
#define MROWS (BATCH*SEQ)   // 90112

typedef unsigned long long u64;

// Scratch: A=(x+pe) fp16, W fp16, QKV fp16
__device__ __half g_Af[(size_t)MROWS*DM];
__device__ __half g_Wf[768*DM];
__device__ __half g_qkv[3ULL*(size_t)MROWS*(size_t)DM];

// ---------------------------------------------------------------------------
// helpers
// ---------------------------------------------------------------------------
__device__ __forceinline__ uint32_t smem_u32(const void* p){
    uint32_t a;
    asm("{ .reg .u64 t; cvta.to.shared.u64 t, %1; cvt.u32.u64 %0, t; }" : "=r"(a) : "l"(p));
    return a;
}
__device__ __forceinline__ uint32_t sw64(uint32_t off){ return off ^ ((off >> 3) & 0x30); }

__device__ __forceinline__ void cpasync16(uint32_t dst, const void* src){
    asm volatile("cp.async.cg.shared.global [%0], [%1], 16;" :: "r"(dst), "l"(src) : "memory");
}
#define CPASYNC_COMMIT() asm volatile("cp.async.commit_group;" ::: "memory")
#define CPASYNC_WAIT(n)  asm volatile("cp.async.wait_group %0;" :: "n"(n) : "memory")

#define LDSM_X4(r0,r1,r2,r3,addr) \
    asm volatile("ldmatrix.sync.aligned.m8n8.x4.shared.b16 {%0,%1,%2,%3}, [%4];" \
        : "=r"(r0),"=r"(r1),"=r"(r2),"=r"(r3) : "r"(addr))
#define LDSM_X4_T(r0,r1,r2,r3,addr) \
    asm volatile("ldmatrix.sync.aligned.m8n8.x4.trans.shared.b16 {%0,%1,%2,%3}, [%4];" \
        : "=r"(r0),"=r"(r1),"=r"(r2),"=r"(r3) : "r"(addr))
#define MMAF16(d,a0,a1,a2,a3,b0,b1) \
    asm volatile("mma.sync.aligned.m16n8k16.row.col.f32.f16.f16.f32 " \
        "{%0,%1,%2,%3},{%4,%5,%6,%7},{%8,%9},{%0,%1,%2,%3};" \
        : "+f"((d)[0]),"+f"((d)[1]),"+f"((d)[2]),"+f"((d)[3]) \
        : "r"(a0),"r"(a1),"r"(a2),"r"(a3),"r"(b0),"r"(b1))

__device__ __forceinline__ uint32_t f22u(float x, float y){
    __half2 t = __floats2half2_rn(x, y);
    return *(uint32_t*)&t;
}

// ---------------------------------------------------------------------------
// Fused prep: W -> fp16 and (x + PE) -> fp16 (PE inline).
// ---------------------------------------------------------------------------
#define WN4 (768*DM/4)                 // 49152
#define AN4 (MROWS*DM/4)               // 5767168
#define PREP_BLOCKS ((WN4 + AN4)/256)  // 22720 exactly

__global__ __launch_bounds__(256) void prep_kernel(
    const float* __restrict__ x,
    const float* __restrict__ wq, const float* __restrict__ wk, const float* __restrict__ wv)
{
    int idx = blockIdx.x * 256 + threadIdx.x;
    if (idx < WN4) {
        int row = idx >> 6;
        const float* w = (row < 256) ? wq : (row < 512) ? wk : wv;
        int lrow = row & 255;
        int c4   = idx & 63;
        float4 v = *(const float4*)(w + (size_t)lrow*DM + c4*4);
        u64 hv = (u64)__half_as_ushort(__float2half(v.x))
               | ((u64)__half_as_ushort(__float2half(v.y)) << 16)
               | ((u64)__half_as_ushort(__float2half(v.z)) << 32)
               | ((u64)__half_as_ushort(__float2half(v.w)) << 48);
        *(u64*)(g_Wf + (size_t)idx*4) = hv;
    } else {
        int e4 = idx - WN4;
        int m  = e4 >> 6;
        int c4 = e4 & 63;
        float4 xa = *(const float4*)(x + (size_t)m*DM + c4*4);
        const float j = (float)(m % NJ);
        const float NEGLOG = -0.035977892078032f;   // -ln(10000)/256
        float e0 = __expf(NEGLOG * (float)(c4*4));
        float e1 = __expf(NEGLOG * (float)(c4*4 + 2));
        float s0, c0, s1, c1;
        __sincosf(j*e0, &s0, &c0);
        __sincosf(j*e1, &s1, &c1);
        u64 hv = (u64)__half_as_ushort(__float2half(xa.x + s0))
               | ((u64)__half_as_ushort(__float2half(xa.y + c0)) << 16)
               | ((u64)__half_as_ushort(__float2half(xa.z + s1)) << 32)
               | ((u64)__half_as_ushort(__float2half(xa.w + c1)) << 48);
        *(u64*)(g_Af + (size_t)e4*4) = hv;
    }
}

// ---------------------------------------------------------------------------
// QKV GEMM: plain fp16 mma.sync. CTA tile 128x128. KC=32, 3-stage cp.async.
// Output stored as fp16.
// ---------------------------------------------------------------------------
#define MT 128
#define NT 128
#define KC 32
#define NCHUNK (DM/KC)                 // 8
#define ARR8K 8192                     // 128 rows x 32 fp16
#define STAGE (2*ARR8K)                // Af, Bf = 16 KB
#define NSTAGE 3
#define GEMM_SMEM (NSTAGE*STAGE + 1024)

__device__ __forceinline__ void gemm_load_chunk(uint32_t uS, int m0, int n0,
                                                int cc, int ss, int tid)
{
    const uint32_t sb = uS + ss*STAGE;
#pragma unroll
    for (int j = 0; j < 4; j++) {
        int idx = j*256 + tid;         // 0..1023
        int arr = idx >> 9;            // 0=Af 1=Bf
        int w   = idx & 511;
        int r   = w >> 2;              // row 0..127
        int seg = w & 3;               // 16B segment
        uint32_t off = sw64((uint32_t)(r*64 + seg*16)) + arr*ARR8K;
        if (arr == 0) {
            cpasync16(sb + off, g_Af + (size_t)(m0 + r)*DM + cc*KC + seg*8);
        } else {
            cpasync16(sb + off, g_Wf + (size_t)(n0 + r)*DM + cc*KC + seg*8);
        }
    }
}

__global__ __launch_bounds__(256, 2) void qkv_mma_kernel(
    const float* __restrict__ bq, const float* __restrict__ bk, const float* __restrict__ bv)
{
    extern __shared__ char dyn_raw[];
    char* dsm = (char*)(((uintptr_t)dyn_raw + 1023) & ~(uintptr_t)1023);
    const uint32_t uS = smem_u32(dsm);

    const int tid  = threadIdx.x;
    const int wid  = tid >> 5;
    const int lane = tid & 31;
    const int wm   = wid & 3;              // 4 m-warps x 32 rows
    const int wn   = wid >> 2;             // 2 n-warps x 64 cols

    const int n0    = blockIdx.x * NT;
    const int m0    = blockIdx.y * MT;
    const int which = n0 >> 8;
    const int ncol0 = n0 & 255;
    const float* bbase = (which == 0) ? bq : (which == 1) ? bk : bv;

    const int a_row = wm*32 + (lane & 15);
    const int a_kb  = (lane >> 4) * 16;
    const int b_row = wn*64 + (lane & 7) + ((lane >> 4) & 1)*8;
    const int b_kb  = ((lane >> 3) & 1) * 16;

    float acc[2][8][4];
#pragma unroll
    for (int i = 0; i < 2; i++)
#pragma unroll
        for (int j = 0; j < 8; j++)
#pragma unroll
            for (int q = 0; q < 4; q++) acc[i][j][q] = 0.f;

    gemm_load_chunk(uS, m0, n0, 0, 0, tid);
    CPASYNC_COMMIT();
    gemm_load_chunk(uS, m0, n0, 1, 1, tid);
    CPASYNC_COMMIT();

    for (int c = 0; c < NCHUNK; c++) {
        if (c + 2 < NCHUNK) {
            CPASYNC_WAIT(1);
            __syncthreads();
            gemm_load_chunk(uS, m0, n0, c + 2, (c + 2) % NSTAGE, tid);
            CPASYNC_COMMIT();
        } else if (c + 1 < NCHUNK) {
            CPASYNC_WAIT(1);
            __syncthreads();
        } else {
            CPASYNC_WAIT(0);
            __syncthreads();
        }

        const uint32_t uAf = uS + (c % NSTAGE)*STAGE;
        const uint32_t uBf = uAf + ARR8K;

#pragma unroll
        for (int k = 0; k < 2; k++) {
            const int kb = k*32;
            uint32_t ao0 = sw64((uint32_t)( a_row      *64 + kb + a_kb));
            uint32_t ao1 = sw64((uint32_t)((a_row + 16)*64 + kb + a_kb));
            uint32_t a0[4], a1[4];
            LDSM_X4(a0[0],a0[1],a0[2],a0[3], uAf + ao0);
            LDSM_X4(a1[0],a1[1],a1[2],a1[3], uAf + ao1);
#pragma unroll
            for (int nt2 = 0; nt2 < 4; nt2++) {
                uint32_t bo = sw64((uint32_t)((b_row + nt2*16)*64 + kb + b_kb));
                uint32_t bf[4];
                LDSM_X4(bf[0], bf[1], bf[2], bf[3], uBf + bo);
                const int nt = nt2*2;
                MMAF16(acc[0][nt  ], a0[0],a0[1],a0[2],a0[3], bf[0],bf[1]);
                MMAF16(acc[1][nt  ], a1[0],a1[1],a1[2],a1[3], bf[0],bf[1]);
                MMAF16(acc[0][nt+1], a0[0],a0[1],a0[2],a0[3], bf[2],bf[3]);
                MMAF16(acc[1][nt+1], a1[0],a1[1],a1[2],a1[3], bf[2],bf[3]);
            }
        }
    }

    // ---- epilogue: bias add + fp16 stores ----
    __half* obase = g_qkv + (size_t)which*MROWS*DM;
    const int mr = m0 + wm*32 + (lane >> 2);
    const int nc = ncol0 + wn*64 + (lane & 3)*2;
#pragma unroll
    for (int mt = 0; mt < 2; mt++) {
#pragma unroll
        for (int nt = 0; nt < 8; nt++) {
            const int col = nc + nt*8;
            const float b0 = bbase[col], b1 = bbase[col+1];
            __half2 h0 = __floats2half2_rn(acc[mt][nt][0] + b0, acc[mt][nt][1] + b1);
            __half2 h1 = __floats2half2_rn(acc[mt][nt][2] + b0, acc[mt][nt][3] + b1);
            *(__half2*)(obase + (size_t)(mr + mt*16    )*DM + col) = h0;
            *(__half2*)(obase + (size_t)(mr + mt*16 + 8)*DM + col) = h1;
        }
    }
}

// ---------------------------------------------------------------------------
// Tensor-core frame-local attention (unchanged from best-known).
// Block = (batch, frame), warp = head.
// ---------------------------------------------------------------------------
#define VT_STRIDE 72   // halves; 144B rows: 16B-aligned, 8-row bank-distinct
#define OS_STRIDE 34   // halves; 17-word rows, conflict-free
#define ATT_SMEM ((HEADS*32*VT_STRIDE + HEADS*32*OS_STRIDE)*2)   // 54272 B

__global__ __launch_bounds__(256, 2) void attention_kernel(float* __restrict__ out)
{
    extern __shared__ __half smh[];
    const int bf   = blockIdx.x;
    const int b    = bf >> 3;
    const int f    = bf & 7;
    const int h    = threadIdx.x >> 5;
    const int lane = threadIdx.x & 31;
    const int g    = lane >> 2;
    const int c    = lane & 3;

    __half* vt = smh + h*(32*VT_STRIDE);
    __half* os = smh + HEADS*(32*VT_STRIDE) + h*(32*OS_STRIDE);

    const size_t row0 = (size_t)b * SEQ + (size_t)f * NJ;
    const __half* Qb = g_qkv + row0*DM + h*HD;
    const __half* Kb = g_qkv + (size_t)MROWS*DM + row0*DM + h*HD;
    const __half* Vb = g_qkv + 2ULL*(size_t)MROWS*DM + row0*DM + h*HD;

#pragma unroll
    for (int kj = 0; kj < NJ; kj++)
        vt[kj*VT_STRIDE + lane] = Vb[(size_t)kj*DM + lane];
#pragma unroll
    for (int r = NJ; r < 32; r++)
        vt[r*VT_STRIDE + lane] = __ushort_as_half(0);
    __syncwarp();

    uint32_t kb[3][2][2];
#pragma unroll
    for (int n = 0; n < 3; n++)
#pragma unroll
        for (int kk = 0; kk < 2; kk++) {
            const __half* p = Kb + (size_t)(n*8 + g)*DM + kk*16 + 2*c;
            kb[n][kk][0] = *(const uint32_t*)p;
            kb[n][kk][1] = *(const uint32_t*)(p + 8);
        }

    uint32_t vb[4][2][2];
    {
        const uint32_t vtb = smem_u32(vt);
        const int vrow = (lane & 7) + ((lane >> 3) & 1)*8;
        const int vcol = (lane >> 4)*8;
#pragma unroll
        for (int np = 0; np < 2; np++)
#pragma unroll
            for (int kk = 0; kk < 2; kk++) {
                uint32_t addr = vtb + (uint32_t)((kk*16 + vrow)*VT_STRIDE + np*16 + vcol)*2;
                LDSM_X4_T(vb[2*np][kk][0], vb[2*np][kk][1],
                          vb[2*np+1][kk][0], vb[2*np+1][kk][1], addr);
            }
    }

    const uint32_t zero2 = 0;
    const float SC = 0.17677669529663687f;

#pragma unroll
    for (int m = 0; m < 2; m++) {
        uint32_t qa[2][4];
#pragma unroll
        for (int kk = 0; kk < 2; kk++) {
            const __half* p = Qb + (size_t)(m*16 + g)*DM + kk*16 + 2*c;
            qa[kk][0] = *(const uint32_t*)p;
            qa[kk][1] = *(const uint32_t*)(p + 8*DM);
            qa[kk][2] = *(const uint32_t*)(p + 8);
            qa[kk][3] = *(const uint32_t*)(p + 8*DM + 8);
        }

        float s[3][4];
#pragma unroll
        for (int n = 0; n < 3; n++) {
            s[n][0] = s[n][1] = s[n][2] = s[n][3] = 0.f;
#pragma unroll
            for (int kk = 0; kk < 2; kk++)
                MMAF16(s[n], qa[kk][0],qa[kk][1],qa[kk][2],qa[kk][3],
                       kb[n][kk][0], kb[n][kk][1]);
        }
#pragma unroll
        for (int n = 0; n < 3; n++)
#pragma unroll
            for (int j = 0; j < 4; j++) s[n][j] *= SC;
        if (c == 3) { s[2][0] = s[2][1] = s[2][2] = s[2][3] = -1e30f; }

        float mxa = fmaxf(fmaxf(s[0][0], s[0][1]),
                    fmaxf(fmaxf(s[1][0], s[1][1]), fmaxf(s[2][0], s[2][1])));
        float mxb = fmaxf(fmaxf(s[0][2], s[0][3]),
                    fmaxf(fmaxf(s[1][2], s[1][3]), fmaxf(s[2][2], s[2][3])));
        mxa = fmaxf(mxa, __shfl_xor_sync(0xffffffffu, mxa, 1));
        mxa = fmaxf(mxa, __shfl_xor_sync(0xffffffffu, mxa, 2));
        mxb = fmaxf(mxb, __shfl_xor_sync(0xffffffffu, mxb, 1));
        mxb = fmaxf(mxb, __shfl_xor_sync(0xffffffffu, mxb, 2));

        float p[3][4];
        float sa = 0.f, sb = 0.f;
#pragma unroll
        for (int n = 0; n < 3; n++) {
            p[n][0] = __expf(s[n][0] - mxa);
            p[n][1] = __expf(s[n][1] - mxa);
            p[n][2] = __expf(s[n][2] - mxb);
            p[n][3] = __expf(s[n][3] - mxb);
            sa += p[n][0] + p[n][1];
            sb += p[n][2] + p[n][3];
        }
        sa += __shfl_xor_sync(0xffffffffu, sa, 1);
        sa += __shfl_xor_sync(0xffffffffu, sa, 2);
        sb += __shfl_xor_sync(0xffffffffu, sb, 1);
        sb += __shfl_xor_sync(0xffffffffu, sb, 2);
        const float inva = 1.f / sa;
        const float invb = 1.f / sb;

        uint32_t pa0[4], pa1[2];
        pa0[0] = f22u(p[0][0], p[0][1]);
        pa0[1] = f22u(p[0][2], p[0][3]);
        pa0[2] = f22u(p[1][0], p[1][1]);
        pa0[3] = f22u(p[1][2], p[1][3]);
        pa1[0] = f22u(p[2][0], p[2][1]);
        pa1[1] = f22u(p[2][2], p[2][3]);

        float o[4][4];
#pragma unroll
        for (int n = 0; n < 4; n++) {
            o[n][0] = o[n][1] = o[n][2] = o[n][3] = 0.f;
            MMAF16(o[n], pa0[0], pa0[1], pa0[2], pa0[3], vb[n][0][0], vb[n][0][1]);
            MMAF16(o[n], pa1[0], pa1[1], zero2,  zero2,  vb[n][1][0], vb[n][1][1]);
        }

        const int ra = m*16 + g, rb = ra + 8;
#pragma unroll
        for (int n = 0; n < 4; n++) {
            *(__half2*)(os + ra*OS_STRIDE + 8*n + 2*c) = __floats2half2_rn(o[n][0]*inva, o[n][1]*inva);
            *(__half2*)(os + rb*OS_STRIDE + 8*n + 2*c) = __floats2half2_rn(o[n][2]*invb, o[n][3]*invb);
        }
    }
    __syncwarp();

#pragma unroll
    for (int kj = 0; kj < NJ; kj++)
        out[(row0 + kj)*DM + h*HD + lane] = __half2float(os[kj*OS_STRIDE + lane]);
}

// ---------------------------------------------------------------------------
extern "C" void kernel_launch(void* const* d_in, const int* in_sizes, int n_in,
                              void* d_out, int out_size)
{
    const float* x  = (const float*)d_in[0];
    const float* wq = (const float*)d_in[1];
    const float* bq = (const float*)d_in[2];
    const float* wk = (const float*)d_in[3];
    const float* bk = (const float*)d_in[4];
    const float* wv = (const float*)d_in[5];
    const float* bv = (const float*)d_in[6];
    float* out = (float*)d_out;

    cudaFuncSetAttribute(qkv_mma_kernel, cudaFuncAttributeMaxDynamicSharedMemorySize, GEMM_SMEM);
    cudaFuncSetAttribute(attention_kernel, cudaFuncAttributeMaxDynamicSharedMemorySize, ATT_SMEM);

    prep_kernel<<<PREP_BLOCKS, 256>>>(x, wq, wk, wv);

    dim3 ggrid(768 / NT, MROWS / MT);   // (6, 704); x-fastest shares A tile in L2
    qkv_mma_kernel<<<ggrid, 256, GEMM_SMEM>>>(bq, bk, bv);

    attention_kernel<<<BATCH * NF, 256, ATT_SMEM>>>(out);
}